// round 6
// baseline (speedup 1.0000x reference)
#include <cuda_runtime.h>
#include <cstdint>

#define N_NODES 100000
#define N_EDGES 800000
#define NGRAPH  512
#define NLAYER  3
#define NB_STAT 1184
#define TB      256

// ---------------- static scratch (zero-initialized at module load) ----------------
__device__ float g_h   [N_NODES * 64];
__device__ float g_Pa  [N_NODES * 32];
__device__ float g_Pb  [N_NODES * 32];
__device__ float g_agg [N_NODES * 64];   // self-cleaning (node_a zeroes after read)
__device__ float g_z1n [N_NODES * 32];
__device__ float g_a2n [N_NODES * 64];
__device__ float g_deg [N_NODES];        // zeroed by k_update_pool each launch
__device__ float g_pool[NGRAPH * 64];    // zeroed by k_out each launch
__device__ float g_cnt [NGRAPH];         // zeroed by k_out each launch
__device__ float g_bpart[NB_STAT * 128];
__device__ float g_s[64];
__device__ float g_t[64];
__device__ unsigned g_tick[4];           // fold tickets (self-resetting)

// ---------------- helpers ----------------
__device__ __forceinline__ void red2(float* p, float a, float b) {
    asm volatile("red.global.add.v2.f32 [%0], {%1, %2};"
                 :: "l"(p), "f"(a), "f"(b) : "memory");
}
__device__ __forceinline__ void red1(float* p, float a) {
    asm volatile("red.global.add.f32 [%0], %1;"
                 :: "l"(p), "f"(a) : "memory");
}
// packed fp32x2
__device__ __forceinline__ uint64_t fdup(float x) {
    uint64_t r; asm("mov.b64 %0, {%1, %1};" : "=l"(r) : "f"(x)); return r;
}
__device__ __forceinline__ void funpack(uint64_t v, float& x, float& y) {
    asm("mov.b64 {%0, %1}, %2;" : "=f"(x), "=f"(y) : "l"(v));
}
__device__ __forceinline__ void ffma2(uint64_t& d, uint64_t a, uint64_t b) {
    asm("fma.rn.f32x2 %0, %1, %2, %0;" : "+l"(d) : "l"(a), "l"(b));
}
__device__ __forceinline__ void lds2x64(uint64_t& a, uint64_t& b, const float* p) {
    uint32_t ad = (uint32_t)__cvta_generic_to_shared(p);
    asm volatile("ld.shared.v2.b64 {%0, %1}, [%2];" : "=l"(a), "=l"(b) : "r"(ad));
}

// ---------------- in-kernel stat fold (threadFenceReduction pattern) ----------------
// red: per-warp partials [8][128]; rd: 8KB scratch (reused dead smem).
// Last-arriving block reduces g_bpart in fixed order (deterministic) into g_s/g_t.
__device__ __forceinline__ void stat_fold(float (*red)[128], double (*rd)[128],
                                          const float* __restrict__ gam,
                                          const float* __restrict__ bet,
                                          int nf, double invcnt, unsigned* tick) {
    __syncthreads();
    int f = threadIdx.x;
    if (f < 128) {
        float S = 0.f;
#pragma unroll
        for (int w = 0; w < 8; w++) S += red[w][f];
        g_bpart[blockIdx.x * 128 + f] = S;
    }
    __threadfence();
    __syncthreads();
    __shared__ int s_last;
    if (f == 0) s_last = (atomicAdd(tick, 1u) == gridDim.x - 1) ? 1 : 0;
    __syncthreads();
    if (!s_last) return;
    int q = f & 31, g = f >> 5;
    double s0 = 0, s1 = 0, s2 = 0, s3 = 0;
    for (int b = g; b < (int)gridDim.x; b += 8) {
        float4 v = __ldcg((const float4*)&g_bpart[b * 128 + q * 4]);
        s0 += (double)v.x; s1 += (double)v.y; s2 += (double)v.z; s3 += (double)v.w;
    }
    rd[g][q * 4 + 0] = s0; rd[g][q * 4 + 1] = s1;
    rd[g][q * 4 + 2] = s2; rd[g][q * 4 + 3] = s3;
    __syncthreads();
    if (f < nf) {
        double S = 0, Q = 0;
#pragma unroll
        for (int g2 = 0; g2 < 8; g2++) { S += rd[g2][f]; Q += rd[g2][64 + f]; }
        double m = S * invcnt;
        double v = Q * invcnt - m * m;
        if (v < 0.0) v = 0.0;
        double inv = rsqrt(v + 1e-5);
        float sc = (float)((double)__ldg(gam + f) * inv);
        g_s[f] = sc;
        g_t[f] = __ldg(bet + f) - (float)m * sc;
    }
    if (f == 0) *tick = 0;
}

// ---------------- h = x @ Win + b ----------------
__global__ void __launch_bounds__(TB) k_lin_in(const float* __restrict__ x,
                                               const float* __restrict__ W,
                                               const float* __restrict__ b) {
    int lane = threadIdx.x & 31;
    int warp = (blockIdx.x * TB + threadIdx.x) >> 5;
    int nw   = (gridDim.x * TB) >> 5;
    float b0 = __ldg(b + lane), b1 = __ldg(b + 32 + lane);
    for (int n = warp; n < N_NODES; n += nw) {
        float h0 = b0, h1 = b1;
#pragma unroll
        for (int k = 0; k < 16; k++) {
            float xv = __ldg(x + n * 16 + k);
            h0 = fmaf(xv, __ldg(W + k * 64 + lane), h0);
            h1 = fmaf(xv, __ldg(W + k * 64 + 32 + lane), h1);
        }
        g_h[n * 64 + lane] = h0;
        g_h[n * 64 + 32 + lane] = h1;
    }
}

// ---------------- in-degree (deg starts zero; re-zeroed by k_update_pool) ----------------
__global__ void k_deg(const int* __restrict__ dst) {
    int i = blockIdx.x * blockDim.x + threadIdx.x;
    int st = gridDim.x * blockDim.x;
    for (int e = i; e < N_EDGES; e += st) red1(&g_deg[__ldg(dst + e)], 1.0f);
}

// ---------------- project h -> Pa,Pb (f32x2 GEMM) ----------------
__device__ __forceinline__ void project_group(const float* __restrict__ W1, int lane,
                                              float* ht, const float h0[4], const float h1[4],
                                              int base) {
    __syncwarp();
    ((float4*)ht)[lane]      = make_float4(h0[0], h0[1], h0[2], h0[3]);
    ((float4*)ht)[lane + 32] = make_float4(h1[0], h1[1], h1[2], h1[3]);
    __syncwarp();
    uint64_t pa01 = 0, pa23 = 0, pb01 = 0, pb23 = 0;
#pragma unroll 8
    for (int k = 0; k < 64; k++) {
        uint64_t v01, v23;
        lds2x64(v01, v23, ht + k * 4);
        uint64_t wa = fdup(__ldg(W1 + k * 32 + lane));
        uint64_t wb = fdup(__ldg(W1 + (64 + k) * 32 + lane));
        ffma2(pa01, v01, wa); ffma2(pa23, v23, wa);
        ffma2(pb01, v01, wb); ffma2(pb23, v23, wb);
    }
    float pa[4], pb[4];
    funpack(pa01, pa[0], pa[1]); funpack(pa23, pa[2], pa[3]);
    funpack(pb01, pb[0], pb[1]); funpack(pb23, pb[2], pb[3]);
#pragma unroll
    for (int i = 0; i < 4; i++) {
        g_Pa[(base + i) * 32 + lane] = pa[i];
        g_Pb[(base + i) * 32 + lane] = pb[i];
    }
}

__global__ void __launch_bounds__(TB) k_project(const float* __restrict__ W1) {
    __shared__ alignas(16) float hT[8][256];
    int lane = threadIdx.x & 31, wib = threadIdx.x >> 5;
    int warp = (blockIdx.x * TB + threadIdx.x) >> 5;
    int nw   = (gridDim.x * TB) >> 5;
    float* ht = hT[wib];
    for (int grp = warp; grp < N_NODES / 4; grp += nw) {
        int base = grp * 4;
        float h0[4], h1[4];
#pragma unroll
        for (int i = 0; i < 4; i++) {
            h0[i] = g_h[(base + i) * 64 + lane];
            h1[i] = g_h[(base + i) * 64 + 32 + lane];
        }
        project_group(W1, lane, ht, h0, h1, base);
    }
}

// ---------------- edge pass A: stats of z1 (+fold) ----------------
__global__ void __launch_bounds__(TB) k_edge_a(const int* __restrict__ dst,
                                               const int* __restrict__ src,
                                               const float* __restrict__ ea,
                                               const float* __restrict__ W1,
                                               const float* __restrict__ b1,
                                               const float* __restrict__ gam,
                                               const float* __restrict__ bet,
                                               double invcnt) {
    __shared__ alignas(16) float red[8][128];
    __shared__ alignas(16) double rd[8][128];
    int lane = threadIdx.x & 31, wib = threadIdx.x >> 5;
    int warp = (blockIdx.x * TB + threadIdx.x) >> 5;
    int nw   = (gridDim.x * TB) >> 5;
    float cw = __ldg(W1 + 128 * 32 + lane);
    float cb = __ldg(b1 + lane);
    float S = 0.f, Q = 0.f;
    for (int grp = warp; grp < N_EDGES / 4; grp += nw) {
        int e0 = grp * 4;
        int d[4], s[4];
        float ev[4], pa[4], pb[4];
#pragma unroll
        for (int i = 0; i < 4; i++) {
            d[i] = __ldg(dst + e0 + i);
            s[i] = __ldg(src + e0 + i);
            ev[i] = __ldg(ea + e0 + i);
        }
#pragma unroll
        for (int i = 0; i < 4; i++) {
            pa[i] = g_Pa[d[i] * 32 + lane];
            pb[i] = g_Pb[s[i] * 32 + lane];
        }
#pragma unroll
        for (int i = 0; i < 4; i++) {
            float z = pa[i] + pb[i] + fmaf(ev[i], cw, cb);
            S += z;
            Q = fmaf(z, z, Q);
        }
    }
    red[wib][lane] = S;       red[wib][32 + lane] = 0.f;
    red[wib][64 + lane] = Q;  red[wib][96 + lane] = 0.f;
    stat_fold(red, rd, gam, bet, 32, invcnt, &g_tick[0]);
}

// ---------------- edge pass B: msg MLP + scatter + stats (+fold) ----------------
__global__ void __launch_bounds__(TB) k_edge_b(const int* __restrict__ dst,
                                               const int* __restrict__ src,
                                               const float* __restrict__ ea,
                                               const float* __restrict__ W1,
                                               const float* __restrict__ b1,
                                               const float* __restrict__ W2,
                                               const float* __restrict__ b2,
                                               const float* __restrict__ gam,
                                               const float* __restrict__ bet,
                                               double invcnt) {
    __shared__ alignas(16) float W2s[2048];      // 32x64 (dead after loop -> fold scratch)
    __shared__ alignas(16) float aT[8][2][128];
    __shared__ alignas(16) float red[8][128];
    int lane = threadIdx.x & 31, wib = threadIdx.x >> 5;
    int warp = (blockIdx.x * TB + threadIdx.x) >> 5;
    int nw   = (gridDim.x * TB) >> 5;

    for (int i = threadIdx.x; i < 2048; i += TB) W2s[i] = __ldg(W2 + i);

    float cw = __ldg(W1 + 128 * 32 + lane);
    float cb = __ldg(b1 + lane);
    float bs = g_s[lane], bt = g_t[lane];
    float2 bb = __ldg((const float2*)b2 + lane);
    uint64_t bbx = fdup(bb.x), bby = fdup(bb.y);
    float ss0 = 0.f, ss1 = 0.f, qq0 = 0.f, qq1 = 0.f;
    __syncthreads();

    int toggle = 0;
    for (int grp = warp; grp < N_EDGES / 4; grp += nw) {
        int e0 = grp * 4;
        int d[4], sr[4];
        float ev[4], pa[4], pb[4];
#pragma unroll
        for (int i = 0; i < 4; i++) {
            d[i]  = __ldg(dst + e0 + i);
            sr[i] = __ldg(src + e0 + i);
            ev[i] = __ldg(ea + e0 + i);
        }
#pragma unroll
        for (int i = 0; i < 4; i++) {
            pa[i] = g_Pa[d[i] * 32 + lane];
            pb[i] = g_Pb[sr[i] * 32 + lane];
        }
        float a[4];
#pragma unroll
        for (int i = 0; i < 4; i++) {
            float z = pa[i] + pb[i] + fmaf(ev[i], cw, cb);
            a[i] = fmaxf(fmaf(z, bs, bt), 0.f);
        }
        float* at = aT[wib][toggle];
        toggle ^= 1;
        ((float4*)at)[lane] = make_float4(a[0], a[1], a[2], a[3]);
        __syncwarp();

        // packed-pair GEMM: edges (0,1) and (2,3) per accumulator
        uint64_t A01x = bbx, A23x = bbx, A01y = bby, A23y = bby;
#pragma unroll
        for (int k = 0; k < 32; k++) {
            uint64_t v01, v23;
            lds2x64(v01, v23, at + k * 4);
            float2 w = ((const float2*)W2s)[k * 32 + lane];
            uint64_t wx = fdup(w.x), wy = fdup(w.y);
            ffma2(A01x, v01, wx); ffma2(A23x, v23, wx);
            ffma2(A01y, v01, wy); ffma2(A23y, v23, wy);
        }
        float o0[4], o1[4];
        funpack(A01x, o0[0], o0[1]); funpack(A23x, o0[2], o0[3]);
        funpack(A01y, o1[0], o1[1]); funpack(A23y, o1[2], o1[3]);
#pragma unroll
        for (int i = 0; i < 4; i++) {
            o0[i] = fmaxf(o0[i], 0.f);
            o1[i] = fmaxf(o1[i], 0.f);
            ss0 += o0[i]; qq0 = fmaf(o0[i], o0[i], qq0);
            ss1 += o1[i]; qq1 = fmaf(o1[i], o1[i], qq1);
            red2(g_agg + d[i] * 64 + 2 * lane, o0[i], o1[i]);
        }
    }
    red[wib][2 * lane]      = ss0;
    red[wib][2 * lane + 1]  = ss1;
    red[wib][64 + 2 * lane] = qq0;
    red[wib][65 + 2 * lane] = qq1;
    stat_fold(red, (double(*)[128])W2s, gam, bet, 64, invcnt, &g_tick[1]);
}

// ---------------- node pass A: z1n = [h, aggN] @ U1 + b; stats(+fold); self-clean agg ----------------
__global__ void __launch_bounds__(TB) k_node_a(const float* __restrict__ U1,
                                               const float* __restrict__ ub1,
                                               const float* __restrict__ gam,
                                               const float* __restrict__ bet,
                                               double invcnt) {
    __shared__ alignas(16) float xT[8][512];     // dead after loop -> fold scratch
    __shared__ alignas(16) float red[8][128];
    int lane = threadIdx.x & 31, wib = threadIdx.x >> 5;
    int warp = (blockIdx.x * TB + threadIdx.x) >> 5;
    int nw   = (gridDim.x * TB) >> 5;
    float s2a = g_s[lane], s2b = g_s[lane + 32];
    float t2a = g_t[lane], t2b = g_t[lane + 32];
    float bbz = __ldg(ub1 + lane);
    uint64_t bz = fdup(bbz);
    float S = 0.f, Q = 0.f;
    float* xt = xT[wib];
    for (int grp = warp; grp < N_NODES / 4; grp += nw) {
        int base = grp * 4;
        float h0[4], h1[4], a0[4], a1[4];
#pragma unroll
        for (int i = 0; i < 4; i++) {
            int n = base + i;
            h0[i] = g_h[n * 64 + lane];
            h1[i] = g_h[n * 64 + 32 + lane];
            float dg = g_deg[n];
            a0[i] = fmaf(s2a, g_agg[n * 64 + lane],      t2a * dg);
            a1[i] = fmaf(s2b, g_agg[n * 64 + 32 + lane], t2b * dg);
            g_agg[n * 64 + lane]      = 0.f;   // self-clean for next layer / next launch
            g_agg[n * 64 + 32 + lane] = 0.f;
        }
        __syncwarp();
        ((float4*)xt)[lane]      = make_float4(h0[0], h0[1], h0[2], h0[3]);
        ((float4*)xt)[lane + 32] = make_float4(h1[0], h1[1], h1[2], h1[3]);
        ((float4*)xt)[lane + 64] = make_float4(a0[0], a0[1], a0[2], a0[3]);
        ((float4*)xt)[lane + 96] = make_float4(a1[0], a1[1], a1[2], a1[3]);
        __syncwarp();
        uint64_t Z01 = bz, Z23 = bz;
#pragma unroll 16
        for (int k = 0; k < 128; k++) {
            uint64_t v01, v23;
            lds2x64(v01, v23, xt + k * 4);
            uint64_t wd = fdup(__ldg(U1 + k * 32 + lane));
            ffma2(Z01, v01, wd);
            ffma2(Z23, v23, wd);
        }
        float z[4];
        funpack(Z01, z[0], z[1]); funpack(Z23, z[2], z[3]);
#pragma unroll
        for (int i = 0; i < 4; i++) {
            g_z1n[(base + i) * 32 + lane] = z[i];
            S += z[i];
            Q = fmaf(z[i], z[i], Q);
        }
    }
    red[wib][lane] = S;       red[wib][32 + lane] = 0.f;
    red[wib][64 + lane] = Q;  red[wib][96 + lane] = 0.f;
    stat_fold(red, (double(*)[128])&xT[0][0], gam, bet, 32, invcnt, &g_tick[2]);
}

// ---------------- node pass B (+fold) ----------------
__global__ void __launch_bounds__(TB) k_node_b(const float* __restrict__ U2,
                                               const float* __restrict__ ub2,
                                               const float* __restrict__ gam,
                                               const float* __restrict__ bet,
                                               double invcnt) {
    __shared__ alignas(16) float U2s[2048];      // dead after loop -> fold scratch
    __shared__ alignas(16) float aT[8][2][128];
    __shared__ alignas(16) float red[8][128];
    int lane = threadIdx.x & 31, wib = threadIdx.x >> 5;
    int warp = (blockIdx.x * TB + threadIdx.x) >> 5;
    int nw   = (gridDim.x * TB) >> 5;
    for (int i = threadIdx.x; i < 2048; i += TB) U2s[i] = __ldg(U2 + i);
    float s3 = g_s[lane], t3 = g_t[lane];
    float2 bb = __ldg((const float2*)ub2 + lane);
    uint64_t bbx = fdup(bb.x), bby = fdup(bb.y);
    float ss0 = 0.f, ss1 = 0.f, qq0 = 0.f, qq1 = 0.f;
    __syncthreads();
    int toggle = 0;
    for (int grp = warp; grp < N_NODES / 4; grp += nw) {
        int base = grp * 4;
        float a[4];
#pragma unroll
        for (int i = 0; i < 4; i++)
            a[i] = fmaxf(fmaf(g_z1n[(base + i) * 32 + lane], s3, t3), 0.f);
        float* at = aT[wib][toggle];
        toggle ^= 1;
        ((float4*)at)[lane] = make_float4(a[0], a[1], a[2], a[3]);
        __syncwarp();
        uint64_t A01x = bbx, A23x = bbx, A01y = bby, A23y = bby;
#pragma unroll
        for (int k = 0; k < 32; k++) {
            uint64_t v01, v23;
            lds2x64(v01, v23, at + k * 4);
            float2 w = ((const float2*)U2s)[k * 32 + lane];
            uint64_t wx = fdup(w.x), wy = fdup(w.y);
            ffma2(A01x, v01, wx); ffma2(A23x, v23, wx);
            ffma2(A01y, v01, wy); ffma2(A23y, v23, wy);
        }
        float o0[4], o1[4];
        funpack(A01x, o0[0], o0[1]); funpack(A23x, o0[2], o0[3]);
        funpack(A01y, o1[0], o1[1]); funpack(A23y, o1[2], o1[3]);
#pragma unroll
        for (int i = 0; i < 4; i++) {
            o0[i] = fmaxf(o0[i], 0.f);
            o1[i] = fmaxf(o1[i], 0.f);
            ((float2*)g_a2n)[(base + i) * 32 + lane] = make_float2(o0[i], o1[i]);
            ss0 += o0[i]; qq0 = fmaf(o0[i], o0[i], qq0);
            ss1 += o1[i]; qq1 = fmaf(o1[i], o1[i], qq1);
        }
    }
    red[wib][2 * lane]      = ss0;
    red[wib][2 * lane + 1]  = ss1;
    red[wib][64 + 2 * lane] = qq0;
    red[wib][65 + 2 * lane] = qq1;
    stat_fold(red, (double(*)[128])U2s, gam, bet, 64, invcnt, &g_tick[3]);
}

// ---------------- h += bn(a2n); project next layer ----------------
__global__ void __launch_bounds__(TB) k_update_proj(const float* __restrict__ W1next) {
    __shared__ alignas(16) float hT[8][256];
    int lane = threadIdx.x & 31, wib = threadIdx.x >> 5;
    int warp = (blockIdx.x * TB + threadIdx.x) >> 5;
    int nw   = (gridDim.x * TB) >> 5;
    float s4a = g_s[lane], s4b = g_s[lane + 32];
    float t4a = g_t[lane], t4b = g_t[lane + 32];
    float* ht = hT[wib];
    for (int grp = warp; grp < N_NODES / 4; grp += nw) {
        int base = grp * 4;
        float h0[4], h1[4];
#pragma unroll
        for (int i = 0; i < 4; i++) {
            int n = base + i;
            h0[i] = g_h[n * 64 + lane]      + fmaf(s4a, g_a2n[n * 64 + lane],      t4a);
            h1[i] = g_h[n * 64 + 32 + lane] + fmaf(s4b, g_a2n[n * 64 + 32 + lane], t4b);
            g_h[n * 64 + lane]      = h0[i];
            g_h[n * 64 + 32 + lane] = h1[i];
        }
        project_group(W1next, lane, ht, h0, h1, base);
    }
}

// ---------------- last layer: h += bn(a2n); pool; zero deg ----------------
__global__ void __launch_bounds__(TB) k_update_pool(const int* __restrict__ batch) {
    int lane = threadIdx.x & 31;
    int warp = (blockIdx.x * TB + threadIdx.x) >> 5;
    int nw   = (gridDim.x * TB) >> 5;
    float s4a = g_s[lane], s4b = g_s[lane + 32];
    float t4a = g_t[lane], t4b = g_t[lane + 32];
    for (int grp = warp; grp < N_NODES / 4; grp += nw) {
        int base = grp * 4;
        float h0[4], h1[4];
        int gg[4];
#pragma unroll
        for (int i = 0; i < 4; i++) {
            int n = base + i;
            h0[i] = g_h[n * 64 + lane]      + fmaf(s4a, g_a2n[n * 64 + lane],      t4a);
            h1[i] = g_h[n * 64 + 32 + lane] + fmaf(s4b, g_a2n[n * 64 + 32 + lane], t4b);
            gg[i] = __ldg(batch + n);
        }
        if (lane < 4) g_deg[base + lane] = 0.f;   // self-clean deg for next launch
        if (gg[0] == gg[3]) {  // batch sorted -> all four equal
            red1(&g_pool[gg[0] * 64 + lane],      h0[0] + h0[1] + h0[2] + h0[3]);
            red1(&g_pool[gg[0] * 64 + 32 + lane], h1[0] + h1[1] + h1[2] + h1[3]);
            if (lane == 0) red1(&g_cnt[gg[0]], 4.0f);
        } else {
#pragma unroll
            for (int i = 0; i < 4; i++) {
                red1(&g_pool[gg[i] * 64 + lane], h0[i]);
                red1(&g_pool[gg[i] * 64 + 32 + lane], h1[i]);
                if (lane == 0) red1(&g_cnt[gg[i]], 1.0f);
            }
        }
    }
}

// ---------------- final head; self-clean pool/cnt ----------------
__global__ void k_out(const float* __restrict__ ow, const float* __restrict__ ob,
                      float* __restrict__ out) {
    int lane = threadIdx.x & 31;
    int gidx = (blockIdx.x * blockDim.x + threadIdx.x) >> 5;
    if (gidx >= NGRAPH) return;
    float c = fmaxf(g_cnt[gidx], 1.0f);
    float v = g_pool[gidx * 64 + lane] * __ldg(ow + lane)
            + g_pool[gidx * 64 + 32 + lane] * __ldg(ow + lane + 32);
#pragma unroll
    for (int off = 16; off > 0; off >>= 1) v += __shfl_down_sync(0xffffffffu, v, off);
    if (lane == 0) out[gidx] = fmaxf(v / c + __ldg(ob), 0.f);
    g_pool[gidx * 64 + lane] = 0.f;
    g_pool[gidx * 64 + 32 + lane] = 0.f;
    if (lane == 0) g_cnt[gidx] = 0.f;
}

// ---------------- launch ----------------
extern "C" void kernel_launch(void* const* d_in, const int* in_sizes, int n_in,
                              void* d_out, int out_size) {
    const float* x       = (const float*)d_in[0];
    const int*   ei      = (const int*)  d_in[1];
    const float* ea      = (const float*)d_in[2];
    const int*   batch   = (const int*)  d_in[3];
    const float* lin_w   = (const float*)d_in[4];
    const float* lin_b   = (const float*)d_in[5];
    const float* msg_w1  = (const float*)d_in[6];
    const float* msg_b1  = (const float*)d_in[7];
    const float* msg_g1  = (const float*)d_in[8];
    const float* msg_be1 = (const float*)d_in[9];
    const float* msg_w2  = (const float*)d_in[10];
    const float* msg_b2  = (const float*)d_in[11];
    const float* msg_g2  = (const float*)d_in[12];
    const float* msg_be2 = (const float*)d_in[13];
    const float* upd_w1  = (const float*)d_in[14];
    const float* upd_b1  = (const float*)d_in[15];
    const float* upd_g1  = (const float*)d_in[16];
    const float* upd_be1 = (const float*)d_in[17];
    const float* upd_w2  = (const float*)d_in[18];
    const float* upd_b2  = (const float*)d_in[19];
    const float* upd_g2  = (const float*)d_in[20];
    const float* upd_be2 = (const float*)d_in[21];
    const float* out_w   = (const float*)d_in[22];
    const float* out_b   = (const float*)d_in[23];

    const int* src = ei;
    const int* dst = ei + N_EDGES;

    const double invE = 1.0 / (double)N_EDGES;
    const double invN = 1.0 / (double)N_NODES;

    k_lin_in<<<NB_STAT, TB>>>(x, lin_w, lin_b);
    k_deg<<<512, TB>>>(dst);
    k_project<<<NB_STAT, TB>>>(msg_w1);

    for (int l = 0; l < NLAYER; l++) {
        const float* W1 = msg_w1 + l * 129 * 32;
        const float* b1 = msg_b1 + l * 32;
        const float* W2 = msg_w2 + l * 32 * 64;
        const float* b2 = msg_b2 + l * 64;
        const float* U1 = upd_w1 + l * 128 * 32;
        const float* v1 = upd_b1 + l * 32;
        const float* U2 = upd_w2 + l * 32 * 64;
        const float* v2 = upd_b2 + l * 64;

        k_edge_a<<<NB_STAT, TB>>>(dst, src, ea, W1, b1,
                                  msg_g1 + l * 32, msg_be1 + l * 32, invE);
        k_edge_b<<<NB_STAT, TB>>>(dst, src, ea, W1, b1, W2, b2,
                                  msg_g2 + l * 64, msg_be2 + l * 64, invE);
        k_node_a<<<NB_STAT, TB>>>(U1, v1,
                                  upd_g1 + l * 32, upd_be1 + l * 32, invN);
        k_node_b<<<NB_STAT, TB>>>(U2, v2,
                                  upd_g2 + l * 64, upd_be2 + l * 64, invN);

        if (l == NLAYER - 1) {
            k_update_pool<<<NB_STAT, TB>>>(batch);
        } else {
            k_update_proj<<<NB_STAT, TB>>>(msg_w1 + (l + 1) * 129 * 32);
        }
    }

    k_out<<<16, 1024>>>(out_w, out_b, (float*)d_out);
}

// round 10
// speedup vs baseline: 1.0616x; 1.0616x over previous
#include <cuda_runtime.h>
#include <cstdint>

#define N_NODES 100000
#define N_EDGES 800000
#define NGRAPH  512
#define NLAYER  3
#define NB_STAT 1184
#define TB      256

// ---------------- static scratch ----------------
__device__ float g_h   [N_NODES * 64];
__device__ float g_Pa  [N_NODES * 32];
__device__ float g_Pb  [N_NODES * 32];
__device__ float g_agg [NLAYER][N_NODES * 64];
__device__ float g_z1n [N_NODES * 32];
__device__ float g_a2n [N_NODES * 64];
__device__ float g_deg [N_NODES];
__device__ float g_pool[NGRAPH * 64];
__device__ float g_cnt [NGRAPH];
__device__ float g_bpart[NB_STAT * 128];
__device__ float g_s[64];
__device__ float g_t[64];

// ---------------- helpers ----------------
__device__ __forceinline__ void red2(float* p, float a, float b) {
    asm volatile("red.global.add.v2.f32 [%0], {%1, %2};"
                 :: "l"(p), "f"(a), "f"(b) : "memory");
}
__device__ __forceinline__ void red1(float* p, float a) {
    asm volatile("red.global.add.f32 [%0], %1;"
                 :: "l"(p), "f"(a) : "memory");
}
// packed fp32x2
__device__ __forceinline__ uint64_t fdup(float x) {
    uint64_t r; asm("mov.b64 %0, {%1, %1};" : "=l"(r) : "f"(x)); return r;
}
__device__ __forceinline__ void funpack(uint64_t v, float& x, float& y) {
    asm("mov.b64 {%0, %1}, %2;" : "=f"(x), "=f"(y) : "l"(v));
}
__device__ __forceinline__ void ffma2(uint64_t& d, uint64_t a, uint64_t b) {
    asm("fma.rn.f32x2 %0, %1, %2, %0;" : "+l"(d) : "l"(a), "l"(b));
}
__device__ __forceinline__ void lds2x64(uint64_t& a, uint64_t& b, const float* p) {
    uint32_t ad = (uint32_t)__cvta_generic_to_shared(p);
    asm volatile("ld.shared.v2.b64 {%0, %1}, [%2];" : "=l"(a), "=l"(b) : "r"(ad));
}

// ---------------- zero accumulated scratch ----------------
__global__ void k_zero() {
    long i  = (long)blockIdx.x * blockDim.x + threadIdx.x;
    long st = (long)gridDim.x * blockDim.x;
    float* aggf = &g_agg[0][0];
    long tot = (long)NLAYER * N_NODES * 64;
    for (long j = i; j < tot; j += st) aggf[j] = 0.f;
    for (long j = i; j < N_NODES; j += st) g_deg[j] = 0.f;
    for (long j = i; j < NGRAPH * 64; j += st) g_pool[j] = 0.f;
    for (long j = i; j < NGRAPH; j += st) g_cnt[j] = 0.f;
}

// ---------------- h = x @ Win + b ----------------
__global__ void __launch_bounds__(TB) k_lin_in(const float* __restrict__ x,
                                               const float* __restrict__ W,
                                               const float* __restrict__ b) {
    int lane = threadIdx.x & 31;
    int warp = (blockIdx.x * TB + threadIdx.x) >> 5;
    int nw   = (gridDim.x * TB) >> 5;
    float b0 = __ldg(b + lane), b1 = __ldg(b + 32 + lane);
    for (int n = warp; n < N_NODES; n += nw) {
        float h0 = b0, h1 = b1;
#pragma unroll
        for (int k = 0; k < 16; k++) {
            float xv = __ldg(x + n * 16 + k);
            h0 = fmaf(xv, __ldg(W + k * 64 + lane), h0);
            h1 = fmaf(xv, __ldg(W + k * 64 + 32 + lane), h1);
        }
        g_h[n * 64 + lane] = h0;
        g_h[n * 64 + 32 + lane] = h1;
    }
}

// ---------------- in-degree ----------------
__global__ void k_deg(const int* __restrict__ dst) {
    int i = blockIdx.x * blockDim.x + threadIdx.x;
    int st = gridDim.x * blockDim.x;
    for (int e = i; e < N_EDGES; e += st) red1(&g_deg[__ldg(dst + e)], 1.0f);
}

// ---------------- block-reduction epilogue ----------------
__device__ __forceinline__ void stat_epilogue(float (*red)[128]) {
    __syncthreads();
    int f = threadIdx.x;
    if (f < 128) {
        float S = 0.f;
#pragma unroll
        for (int w = 0; w < 8; w++) S += red[w][f];
        g_bpart[blockIdx.x * 128 + f] = S;
    }
}

// ---------------- project h -> Pa,Pb (packed FMA) ----------------
__device__ __forceinline__ void project_group(const float* __restrict__ W1, int lane,
                                              float* ht, const float h0[4], const float h1[4],
                                              int base) {
    __syncwarp();
    ((float4*)ht)[lane]      = make_float4(h0[0], h0[1], h0[2], h0[3]);
    ((float4*)ht)[lane + 32] = make_float4(h1[0], h1[1], h1[2], h1[3]);
    __syncwarp();
    uint64_t pa01 = 0, pa23 = 0, pb01 = 0, pb23 = 0;
#pragma unroll 8
    for (int k = 0; k < 64; k++) {
        uint64_t v01, v23;
        lds2x64(v01, v23, ht + k * 4);
        uint64_t wa = fdup(__ldg(W1 + k * 32 + lane));
        uint64_t wb = fdup(__ldg(W1 + (64 + k) * 32 + lane));
        ffma2(pa01, v01, wa); ffma2(pa23, v23, wa);
        ffma2(pb01, v01, wb); ffma2(pb23, v23, wb);
    }
    float pa[4], pb[4];
    funpack(pa01, pa[0], pa[1]); funpack(pa23, pa[2], pa[3]);
    funpack(pb01, pb[0], pb[1]); funpack(pb23, pb[2], pb[3]);
#pragma unroll
    for (int i = 0; i < 4; i++) {
        g_Pa[(base + i) * 32 + lane] = pa[i];
        g_Pb[(base + i) * 32 + lane] = pb[i];
    }
}

__global__ void __launch_bounds__(TB) k_project(const float* __restrict__ W1) {
    __shared__ alignas(16) float hT[8][256];
    int lane = threadIdx.x & 31, wib = threadIdx.x >> 5;
    int warp = (blockIdx.x * TB + threadIdx.x) >> 5;
    int nw   = (gridDim.x * TB) >> 5;
    float* ht = hT[wib];
    for (int grp = warp; grp < N_NODES / 4; grp += nw) {
        int base = grp * 4;
        float h0[4], h1[4];
#pragma unroll
        for (int i = 0; i < 4; i++) {
            h0[i] = g_h[(base + i) * 64 + lane];
            h1[i] = g_h[(base + i) * 64 + 32 + lane];
        }
        project_group(W1, lane, ht, h0, h1, base);
    }
}

// ---------------- edge pass A: stats of z1 (unchanged scalar) ----------------
__global__ void __launch_bounds__(TB) k_edge_a(const int* __restrict__ dst,
                                               const int* __restrict__ src,
                                               const float* __restrict__ ea,
                                               const float* __restrict__ W1,
                                               const float* __restrict__ b1) {
    __shared__ float red[8][128];
    int lane = threadIdx.x & 31, wib = threadIdx.x >> 5;
    int warp = (blockIdx.x * TB + threadIdx.x) >> 5;
    int nw   = (gridDim.x * TB) >> 5;
    float cw = __ldg(W1 + 128 * 32 + lane);
    float cb = __ldg(b1 + lane);
    float S = 0.f, Q = 0.f;
    for (int grp = warp; grp < N_EDGES / 4; grp += nw) {
        int e0 = grp * 4;
        int d[4], s[4];
        float ev[4], pa[4], pb[4];
#pragma unroll
        for (int i = 0; i < 4; i++) {
            d[i] = __ldg(dst + e0 + i);
            s[i] = __ldg(src + e0 + i);
            ev[i] = __ldg(ea + e0 + i);
        }
#pragma unroll
        for (int i = 0; i < 4; i++) {
            pa[i] = g_Pa[d[i] * 32 + lane];
            pb[i] = g_Pb[s[i] * 32 + lane];
        }
#pragma unroll
        for (int i = 0; i < 4; i++) {
            float z = pa[i] + pb[i] + fmaf(ev[i], cw, cb);
            S += z;
            Q = fmaf(z, z, Q);
        }
    }
    red[wib][lane] = S;       red[wib][32 + lane] = 0.f;
    red[wib][64 + lane] = Q;  red[wib][96 + lane] = 0.f;
    stat_epilogue(red);
}

// ---------------- BN fold: wide single-block reduce ----------------
__global__ void __launch_bounds__(512) k_bn(const float* __restrict__ gam,
                                            const float* __restrict__ bet,
                                            int nf, double invcnt) {
    __shared__ double red[16][128];
    __shared__ double fin[128];
    int tid = threadIdx.x;
    int q = tid & 31;
    int g = tid >> 5;
    double s0 = 0.0, s1 = 0.0, s2 = 0.0, s3 = 0.0;
    for (int b = g; b < NB_STAT; b += 16) {
        float4 v = *(const float4*)&g_bpart[b * 128 + q * 4];
        s0 += (double)v.x; s1 += (double)v.y; s2 += (double)v.z; s3 += (double)v.w;
    }
    red[g][q * 4 + 0] = s0;
    red[g][q * 4 + 1] = s1;
    red[g][q * 4 + 2] = s2;
    red[g][q * 4 + 3] = s3;
    __syncthreads();
    if (tid < 128) {
        double S = 0.0;
#pragma unroll
        for (int g2 = 0; g2 < 16; g2++) S += red[g2][tid];
        fin[tid] = S;
    }
    __syncthreads();
    if (tid < nf) {
        double m = fin[tid] * invcnt;
        double v = fin[64 + tid] * invcnt - m * m;
        if (v < 0.0) v = 0.0;
        double inv = rsqrt(v + 1e-5);
        float sc = (float)((double)__ldg(gam + tid) * inv);
        g_s[tid] = sc;
        g_t[tid] = __ldg(bet + tid) - (float)m * sc;
    }
}

// ---------------- edge pass B: msg MLP + scatter + stats (packed FMA, dup weights) ----------------
__global__ void __launch_bounds__(TB) k_edge_b(const int* __restrict__ dst,
                                               const int* __restrict__ src,
                                               const float* __restrict__ ea,
                                               const float* __restrict__ W1,
                                               const float* __restrict__ b1,
                                               const float* __restrict__ W2,
                                               const float* __restrict__ b2,
                                               int layer) {
    __shared__ alignas(16) ulonglong2 W2d[1024];   // [k][lane] = (dup(w.x), dup(w.y)), 16KB
    __shared__ alignas(16) float aT[8][2][128];
    __shared__ float red[8][128];
    int lane = threadIdx.x & 31, wib = threadIdx.x >> 5;
    int warp = (blockIdx.x * TB + threadIdx.x) >> 5;
    int nw   = (gridDim.x * TB) >> 5;
    float* agg = &g_agg[layer][0];

    // duplicate W2 columns into packed pairs
    for (int i = threadIdx.x; i < 1024; i += TB) {
        float2 w = __ldg((const float2*)W2 + i);
        W2d[i] = make_ulonglong2(fdup(w.x), fdup(w.y));
    }

    float cw = __ldg(W1 + 128 * 32 + lane);
    float cb = __ldg(b1 + lane);
    float bs = g_s[lane], bt = g_t[lane];
    float2 bb = __ldg((const float2*)b2 + lane);
    uint64_t bbx = fdup(bb.x), bby = fdup(bb.y);
    float ss0 = 0.f, ss1 = 0.f, qq0 = 0.f, qq1 = 0.f;
    __syncthreads();

    int toggle = 0;
    for (int grp = warp; grp < N_EDGES / 4; grp += nw) {
        int e0 = grp * 4;
        int d[4], sr[4];
        float ev[4], pa[4], pb[4];
#pragma unroll
        for (int i = 0; i < 4; i++) {
            d[i]  = __ldg(dst + e0 + i);
            sr[i] = __ldg(src + e0 + i);
            ev[i] = __ldg(ea + e0 + i);
        }
#pragma unroll
        for (int i = 0; i < 4; i++) {
            pa[i] = g_Pa[d[i] * 32 + lane];
            pb[i] = g_Pb[sr[i] * 32 + lane];
        }
        float a[4];
#pragma unroll
        for (int i = 0; i < 4; i++) {
            float z = pa[i] + pb[i] + fmaf(ev[i], cw, cb);
            a[i] = fmaxf(fmaf(z, bs, bt), 0.f);
        }
        float* at = aT[wib][toggle];
        toggle ^= 1;
        ((float4*)at)[lane] = make_float4(a[0], a[1], a[2], a[3]);
        __syncwarp();

        uint64_t A01x = bbx, A23x = bbx, A01y = bby, A23y = bby;
#pragma unroll
        for (int k = 0; k < 32; k++) {
            uint64_t v01, v23;
            lds2x64(v01, v23, at + k * 4);
            ulonglong2 wd = W2d[k * 32 + lane];
            ffma2(A01x, v01, wd.x); ffma2(A23x, v23, wd.x);
            ffma2(A01y, v01, wd.y); ffma2(A23y, v23, wd.y);
        }
        float o0[4], o1[4];
        funpack(A01x, o0[0], o0[1]); funpack(A23x, o0[2], o0[3]);
        funpack(A01y, o1[0], o1[1]); funpack(A23y, o1[2], o1[3]);
#pragma unroll
        for (int i = 0; i < 4; i++) {
            o0[i] = fmaxf(o0[i], 0.f);
            o1[i] = fmaxf(o1[i], 0.f);
            ss0 += o0[i]; qq0 = fmaf(o0[i], o0[i], qq0);
            ss1 += o1[i]; qq1 = fmaf(o1[i], o1[i], qq1);
            red2(agg + d[i] * 64 + 2 * lane, o0[i], o1[i]);
        }
    }
    red[wib][2 * lane]      = ss0;
    red[wib][2 * lane + 1]  = ss1;
    red[wib][64 + 2 * lane] = qq0;
    red[wib][65 + 2 * lane] = qq1;
    stat_epilogue(red);
}

// ---------------- node pass A: z1n = [h, aggN] @ U1 + b ; stats (packed FMA) ----------------
__global__ void __launch_bounds__(TB) k_node_a(const float* __restrict__ U1,
                                               const float* __restrict__ ub1,
                                               int layer) {
    __shared__ alignas(16) float xT[8][512];
    __shared__ float red[8][128];
    int lane = threadIdx.x & 31, wib = threadIdx.x >> 5;
    int warp = (blockIdx.x * TB + threadIdx.x) >> 5;
    int nw   = (gridDim.x * TB) >> 5;
    const float* agg = &g_agg[layer][0];
    float s2a = g_s[lane], s2b = g_s[lane + 32];
    float t2a = g_t[lane], t2b = g_t[lane + 32];
    float bbz = __ldg(ub1 + lane);
    uint64_t bz = fdup(bbz);
    float S = 0.f, Q = 0.f;
    float* xt = xT[wib];
    for (int grp = warp; grp < N_NODES / 4; grp += nw) {
        int base = grp * 4;
        float h0[4], h1[4], a0[4], a1[4];
#pragma unroll
        for (int i = 0; i < 4; i++) {
            int n = base + i;
            h0[i] = g_h[n * 64 + lane];
            h1[i] = g_h[n * 64 + 32 + lane];
            float dg = g_deg[n];
            a0[i] = fmaf(s2a, agg[n * 64 + lane],      t2a * dg);
            a1[i] = fmaf(s2b, agg[n * 64 + 32 + lane], t2b * dg);
        }
        __syncwarp();
        ((float4*)xt)[lane]      = make_float4(h0[0], h0[1], h0[2], h0[3]);
        ((float4*)xt)[lane + 32] = make_float4(h1[0], h1[1], h1[2], h1[3]);
        ((float4*)xt)[lane + 64] = make_float4(a0[0], a0[1], a0[2], a0[3]);
        ((float4*)xt)[lane + 96] = make_float4(a1[0], a1[1], a1[2], a1[3]);
        __syncwarp();
        uint64_t Z01 = bz, Z23 = bz;
#pragma unroll 16
        for (int k = 0; k < 128; k++) {
            uint64_t v01, v23;
            lds2x64(v01, v23, xt + k * 4);
            uint64_t wd = fdup(__ldg(U1 + k * 32 + lane));
            ffma2(Z01, v01, wd);
            ffma2(Z23, v23, wd);
        }
        float z[4];
        funpack(Z01, z[0], z[1]); funpack(Z23, z[2], z[3]);
#pragma unroll
        for (int i = 0; i < 4; i++) {
            g_z1n[(base + i) * 32 + lane] = z[i];
            S += z[i];
            Q = fmaf(z[i], z[i], Q);
        }
    }
    red[wib][lane] = S;       red[wib][32 + lane] = 0.f;
    red[wib][64 + lane] = Q;  red[wib][96 + lane] = 0.f;
    stat_epilogue(red);
}

// ---------------- node pass B (packed FMA, dup weights) ----------------
__global__ void __launch_bounds__(TB) k_node_b(const float* __restrict__ U2,
                                               const float* __restrict__ ub2) {
    __shared__ alignas(16) ulonglong2 U2d[1024];   // 16KB
    __shared__ alignas(16) float aT[8][2][128];
    __shared__ float red[8][128];
    int lane = threadIdx.x & 31, wib = threadIdx.x >> 5;
    int warp = (blockIdx.x * TB + threadIdx.x) >> 5;
    int nw   = (gridDim.x * TB) >> 5;
    for (int i = threadIdx.x; i < 1024; i += TB) {
        float2 w = __ldg((const float2*)U2 + i);
        U2d[i] = make_ulonglong2(fdup(w.x), fdup(w.y));
    }
    float s3 = g_s[lane], t3 = g_t[lane];
    float2 bb = __ldg((const float2*)ub2 + lane);
    uint64_t bbx = fdup(bb.x), bby = fdup(bb.y);
    float ss0 = 0.f, ss1 = 0.f, qq0 = 0.f, qq1 = 0.f;
    __syncthreads();
    int toggle = 0;
    for (int grp = warp; grp < N_NODES / 4; grp += nw) {
        int base = grp * 4;
        float a[4];
#pragma unroll
        for (int i = 0; i < 4; i++)
            a[i] = fmaxf(fmaf(g_z1n[(base + i) * 32 + lane], s3, t3), 0.f);
        float* at = aT[wib][toggle];
        toggle ^= 1;
        ((float4*)at)[lane] = make_float4(a[0], a[1], a[2], a[3]);
        __syncwarp();
        uint64_t A01x = bbx, A23x = bbx, A01y = bby, A23y = bby;
#pragma unroll
        for (int k = 0; k < 32; k++) {
            uint64_t v01, v23;
            lds2x64(v01, v23, at + k * 4);
            ulonglong2 wd = U2d[k * 32 + lane];
            ffma2(A01x, v01, wd.x); ffma2(A23x, v23, wd.x);
            ffma2(A01y, v01, wd.y); ffma2(A23y, v23, wd.y);
        }
        float o0[4], o1[4];
        funpack(A01x, o0[0], o0[1]); funpack(A23x, o0[2], o0[3]);
        funpack(A01y, o1[0], o1[1]); funpack(A23y, o1[2], o1[3]);
#pragma unroll
        for (int i = 0; i < 4; i++) {
            o0[i] = fmaxf(o0[i], 0.f);
            o1[i] = fmaxf(o1[i], 0.f);
            ((float2*)g_a2n)[(base + i) * 32 + lane] = make_float2(o0[i], o1[i]);
            ss0 += o0[i]; qq0 = fmaf(o0[i], o0[i], qq0);
            ss1 += o1[i]; qq1 = fmaf(o1[i], o1[i], qq1);
        }
    }
    red[wib][2 * lane]      = ss0;
    red[wib][2 * lane + 1]  = ss1;
    red[wib][64 + 2 * lane] = qq0;
    red[wib][65 + 2 * lane] = qq1;
    stat_epilogue(red);
}

// ---------------- h += bn(a2n); project next layer ----------------
__global__ void __launch_bounds__(TB) k_update_proj(const float* __restrict__ W1next) {
    __shared__ alignas(16) float hT[8][256];
    int lane = threadIdx.x & 31, wib = threadIdx.x >> 5;
    int warp = (blockIdx.x * TB + threadIdx.x) >> 5;
    int nw   = (gridDim.x * TB) >> 5;
    float s4a = g_s[lane], s4b = g_s[lane + 32];
    float t4a = g_t[lane], t4b = g_t[lane + 32];
    float* ht = hT[wib];
    for (int grp = warp; grp < N_NODES / 4; grp += nw) {
        int base = grp * 4;
        float h0[4], h1[4];
#pragma unroll
        for (int i = 0; i < 4; i++) {
            int n = base + i;
            h0[i] = g_h[n * 64 + lane]      + fmaf(s4a, g_a2n[n * 64 + lane],      t4a);
            h1[i] = g_h[n * 64 + 32 + lane] + fmaf(s4b, g_a2n[n * 64 + 32 + lane], t4b);
            g_h[n * 64 + lane]      = h0[i];
            g_h[n * 64 + 32 + lane] = h1[i];
        }
        project_group(W1next, lane, ht, h0, h1, base);
    }
}

// ---------------- last layer: h += bn(a2n); mean-pool scatter ----------------
__global__ void __launch_bounds__(TB) k_update_pool(const int* __restrict__ batch) {
    int lane = threadIdx.x & 31;
    int warp = (blockIdx.x * TB + threadIdx.x) >> 5;
    int nw   = (gridDim.x * TB) >> 5;
    float s4a = g_s[lane], s4b = g_s[lane + 32];
    float t4a = g_t[lane], t4b = g_t[lane + 32];
    for (int grp = warp; grp < N_NODES / 4; grp += nw) {
        int base = grp * 4;
        float h0[4], h1[4];
        int gg[4];
#pragma unroll
        for (int i = 0; i < 4; i++) {
            int n = base + i;
            h0[i] = g_h[n * 64 + lane]      + fmaf(s4a, g_a2n[n * 64 + lane],      t4a);
            h1[i] = g_h[n * 64 + 32 + lane] + fmaf(s4b, g_a2n[n * 64 + 32 + lane], t4b);
            gg[i] = __ldg(batch + n);
        }
        if (gg[0] == gg[3]) {
            red1(&g_pool[gg[0] * 64 + lane],      h0[0] + h0[1] + h0[2] + h0[3]);
            red1(&g_pool[gg[0] * 64 + 32 + lane], h1[0] + h1[1] + h1[2] + h1[3]);
            if (lane == 0) red1(&g_cnt[gg[0]], 4.0f);
        } else {
#pragma unroll
            for (int i = 0; i < 4; i++) {
                red1(&g_pool[gg[i] * 64 + lane], h0[i]);
                red1(&g_pool[gg[i] * 64 + 32 + lane], h1[i]);
                if (lane == 0) red1(&g_cnt[gg[i]], 1.0f);
            }
        }
    }
}

// ---------------- final head ----------------
__global__ void k_out(const float* __restrict__ ow, const float* __restrict__ ob,
                      float* __restrict__ out) {
    int lane = threadIdx.x & 31;
    int gidx = (blockIdx.x * blockDim.x + threadIdx.x) >> 5;
    if (gidx >= NGRAPH) return;
    float c = fmaxf(g_cnt[gidx], 1.0f);
    float v = g_pool[gidx * 64 + lane] * __ldg(ow + lane)
            + g_pool[gidx * 64 + 32 + lane] * __ldg(ow + lane + 32);
#pragma unroll
    for (int off = 16; off > 0; off >>= 1) v += __shfl_down_sync(0xffffffffu, v, off);
    if (lane == 0) out[gidx] = fmaxf(v / c + __ldg(ob), 0.f);
}

// ---------------- launch ----------------
extern "C" void kernel_launch(void* const* d_in, const int* in_sizes, int n_in,
                              void* d_out, int out_size) {
    const float* x       = (const float*)d_in[0];
    const int*   ei      = (const int*)  d_in[1];
    const float* ea      = (const float*)d_in[2];
    const int*   batch   = (const int*)  d_in[3];
    const float* lin_w   = (const float*)d_in[4];
    const float* lin_b   = (const float*)d_in[5];
    const float* msg_w1  = (const float*)d_in[6];
    const float* msg_b1  = (const float*)d_in[7];
    const float* msg_g1  = (const float*)d_in[8];
    const float* msg_be1 = (const float*)d_in[9];
    const float* msg_w2  = (const float*)d_in[10];
    const float* msg_b2  = (const float*)d_in[11];
    const float* msg_g2  = (const float*)d_in[12];
    const float* msg_be2 = (const float*)d_in[13];
    const float* upd_w1  = (const float*)d_in[14];
    const float* upd_b1  = (const float*)d_in[15];
    const float* upd_g1  = (const float*)d_in[16];
    const float* upd_be1 = (const float*)d_in[17];
    const float* upd_w2  = (const float*)d_in[18];
    const float* upd_b2  = (const float*)d_in[19];
    const float* upd_g2  = (const float*)d_in[20];
    const float* upd_be2 = (const float*)d_in[21];
    const float* out_w   = (const float*)d_in[22];
    const float* out_b   = (const float*)d_in[23];

    const int* src = ei;
    const int* dst = ei + N_EDGES;

    const double invE = 1.0 / (double)N_EDGES;
    const double invN = 1.0 / (double)N_NODES;

    k_zero<<<512, TB>>>();
    k_lin_in<<<NB_STAT, TB>>>(x, lin_w, lin_b);
    k_deg<<<512, TB>>>(dst);
    k_project<<<NB_STAT, TB>>>(msg_w1);

    for (int l = 0; l < NLAYER; l++) {
        const float* W1 = msg_w1 + l * 129 * 32;
        const float* b1 = msg_b1 + l * 32;
        const float* W2 = msg_w2 + l * 32 * 64;
        const float* b2 = msg_b2 + l * 64;
        const float* U1 = upd_w1 + l * 128 * 32;
        const float* v1 = upd_b1 + l * 32;
        const float* U2 = upd_w2 + l * 32 * 64;
        const float* v2 = upd_b2 + l * 64;

        k_edge_a<<<NB_STAT, TB>>>(dst, src, ea, W1, b1);
        k_bn<<<1, 512>>>(msg_g1 + l * 32, msg_be1 + l * 32, 32, invE);
        k_edge_b<<<NB_STAT, TB>>>(dst, src, ea, W1, b1, W2, b2, l);
        k_bn<<<1, 512>>>(msg_g2 + l * 64, msg_be2 + l * 64, 64, invE);
        k_node_a<<<NB_STAT, TB>>>(U1, v1, l);
        k_bn<<<1, 512>>>(upd_g1 + l * 32, upd_be1 + l * 32, 32, invN);
        k_node_b<<<NB_STAT, TB>>>(U2, v2);
        k_bn<<<1, 512>>>(upd_g2 + l * 64, upd_be2 + l * 64, 64, invN);

        if (l == NLAYER - 1) {
            k_update_pool<<<NB_STAT, TB>>>(batch);
        } else {
            k_update_proj<<<NB_STAT, TB>>>(msg_w1 + (l + 1) * 129 * 32);
        }
    }

    k_out<<<16, 1024>>>(out_w, out_b, (float*)d_out);
}

// round 11
// speedup vs baseline: 1.1074x; 1.0432x over previous
#include <cuda_runtime.h>
#include <cstdint>

#define N_NODES 100000
#define N_EDGES 800000
#define NGRAPH  512
#define NLAYER  3
#define NB_STAT 1184
#define TB      256

// ---------------- static scratch (zero-initialized at module load; self-cleaning) ----------------
__device__ float g_h   [N_NODES * 64];
__device__ float g_Pa  [N_NODES * 32];
__device__ float g_Pb  [N_NODES * 32];
__device__ float g_agg [N_NODES * 64];   // self-cleaned by k_node_a after read
__device__ float g_z1n [N_NODES * 32];
__device__ float g_a2n [N_NODES * 64];
__device__ float g_deg [N_NODES];        // re-zeroed by k_update_pool
__device__ float g_pool[NGRAPH * 64];    // re-zeroed by k_out
__device__ float g_cnt [NGRAPH];         // re-zeroed by k_out
__device__ float g_bpart[NB_STAT * 128];
__device__ float g_s[64];
__device__ float g_t[64];

// ---------------- helpers ----------------
__device__ __forceinline__ void red2(float* p, float a, float b) {
    asm volatile("red.global.add.v2.f32 [%0], {%1, %2};"
                 :: "l"(p), "f"(a), "f"(b) : "memory");
}
__device__ __forceinline__ void red1(float* p, float a) {
    asm volatile("red.global.add.f32 [%0], %1;"
                 :: "l"(p), "f"(a) : "memory");
}

// ---------------- h = x @ Win + b ----------------
__global__ void __launch_bounds__(TB) k_lin_in(const float* __restrict__ x,
                                               const float* __restrict__ W,
                                               const float* __restrict__ b) {
    int lane = threadIdx.x & 31;
    int warp = (blockIdx.x * TB + threadIdx.x) >> 5;
    int nw   = (gridDim.x * TB) >> 5;
    float b0 = __ldg(b + lane), b1 = __ldg(b + 32 + lane);
    for (int n = warp; n < N_NODES; n += nw) {
        float h0 = b0, h1 = b1;
#pragma unroll
        for (int k = 0; k < 16; k++) {
            float xv = __ldg(x + n * 16 + k);
            h0 = fmaf(xv, __ldg(W + k * 64 + lane), h0);
            h1 = fmaf(xv, __ldg(W + k * 64 + 32 + lane), h1);
        }
        g_h[n * 64 + lane] = h0;
        g_h[n * 64 + 32 + lane] = h1;
    }
}

// ---------------- in-degree (deg is zero on entry every launch) ----------------
__global__ void k_deg(const int* __restrict__ dst) {
    int i = blockIdx.x * blockDim.x + threadIdx.x;
    int st = gridDim.x * blockDim.x;
    for (int e = i; e < N_EDGES; e += st) red1(&g_deg[__ldg(dst + e)], 1.0f);
}

// ---------------- block-reduction epilogue ----------------
__device__ __forceinline__ void stat_epilogue(float (*red)[128]) {
    __syncthreads();
    int f = threadIdx.x;
    if (f < 128) {
        float S = 0.f;
#pragma unroll
        for (int w = 0; w < 8; w++) S += red[w][f];
        g_bpart[blockIdx.x * 128 + f] = S;
    }
}

// ---------------- project h -> Pa,Pb (LDS.128 broadcast GEMM, scalar FMA) ----------------
__device__ __forceinline__ void project_group(const float* __restrict__ W1, int lane,
                                              float* ht, const float h0[4], const float h1[4],
                                              int base) {
    __syncwarp();
    ((float4*)ht)[lane]      = make_float4(h0[0], h0[1], h0[2], h0[3]);
    ((float4*)ht)[lane + 32] = make_float4(h1[0], h1[1], h1[2], h1[3]);
    __syncwarp();
    float pa[4] = {0, 0, 0, 0}, pb[4] = {0, 0, 0, 0};
#pragma unroll 16
    for (int k = 0; k < 64; k++) {
        float4 hv = ((const float4*)ht)[k];
        float wa = __ldg(W1 + k * 32 + lane);
        float wb = __ldg(W1 + (64 + k) * 32 + lane);
        pa[0] = fmaf(hv.x, wa, pa[0]); pb[0] = fmaf(hv.x, wb, pb[0]);
        pa[1] = fmaf(hv.y, wa, pa[1]); pb[1] = fmaf(hv.y, wb, pb[1]);
        pa[2] = fmaf(hv.z, wa, pa[2]); pb[2] = fmaf(hv.z, wb, pb[2]);
        pa[3] = fmaf(hv.w, wa, pa[3]); pb[3] = fmaf(hv.w, wb, pb[3]);
    }
#pragma unroll
    for (int i = 0; i < 4; i++) {
        g_Pa[(base + i) * 32 + lane] = pa[i];
        g_Pb[(base + i) * 32 + lane] = pb[i];
    }
}

__global__ void __launch_bounds__(TB) k_project(const float* __restrict__ W1) {
    __shared__ float hT[8][256];
    int lane = threadIdx.x & 31, wib = threadIdx.x >> 5;
    int warp = (blockIdx.x * TB + threadIdx.x) >> 5;
    int nw   = (gridDim.x * TB) >> 5;
    float* ht = hT[wib];
    for (int grp = warp; grp < N_NODES / 4; grp += nw) {
        int base = grp * 4;
        float h0[4], h1[4];
#pragma unroll
        for (int i = 0; i < 4; i++) {
            h0[i] = g_h[(base + i) * 64 + lane];
            h1[i] = g_h[(base + i) * 64 + 32 + lane];
        }
        project_group(W1, lane, ht, h0, h1, base);
    }
}

// ---------------- edge pass A: stats of z1 (8 edges per warp-iteration for MLP) ----------------
__global__ void __launch_bounds__(TB) k_edge_a(const int* __restrict__ dst,
                                               const int* __restrict__ src,
                                               const float* __restrict__ ea,
                                               const float* __restrict__ W1,
                                               const float* __restrict__ b1) {
    __shared__ float red[8][128];
    int lane = threadIdx.x & 31, wib = threadIdx.x >> 5;
    int warp = (blockIdx.x * TB + threadIdx.x) >> 5;
    int nw   = (gridDim.x * TB) >> 5;
    float cw = __ldg(W1 + 128 * 32 + lane);
    float cb = __ldg(b1 + lane);
    float S = 0.f, Q = 0.f;
    for (int grp = warp; grp < N_EDGES / 8; grp += nw) {
        int e0 = grp * 8;
        int d[8], s[8];
        float ev[8], pa[8], pb[8];
#pragma unroll
        for (int i = 0; i < 8; i++) {
            d[i] = __ldg(dst + e0 + i);
            s[i] = __ldg(src + e0 + i);
            ev[i] = __ldg(ea + e0 + i);
        }
#pragma unroll
        for (int i = 0; i < 8; i++) pa[i] = g_Pa[d[i] * 32 + lane];
#pragma unroll
        for (int i = 0; i < 8; i++) pb[i] = g_Pb[s[i] * 32 + lane];
#pragma unroll
        for (int i = 0; i < 8; i++) {
            float z = pa[i] + pb[i] + fmaf(ev[i], cw, cb);
            S += z;
            Q = fmaf(z, z, Q);
        }
    }
    red[wib][lane] = S;       red[wib][32 + lane] = 0.f;
    red[wib][64 + lane] = Q;  red[wib][96 + lane] = 0.f;
    stat_epilogue(red);
}

// ---------------- BN fold: wide single-block reduce ----------------
__global__ void __launch_bounds__(512) k_bn(const float* __restrict__ gam,
                                            const float* __restrict__ bet,
                                            int nf, double invcnt) {
    __shared__ double red[16][128];
    __shared__ double fin[128];
    int tid = threadIdx.x;
    int q = tid & 31;
    int g = tid >> 5;
    double s0 = 0.0, s1 = 0.0, s2 = 0.0, s3 = 0.0;
    for (int b = g; b < NB_STAT; b += 16) {
        float4 v = *(const float4*)&g_bpart[b * 128 + q * 4];
        s0 += (double)v.x; s1 += (double)v.y; s2 += (double)v.z; s3 += (double)v.w;
    }
    red[g][q * 4 + 0] = s0;
    red[g][q * 4 + 1] = s1;
    red[g][q * 4 + 2] = s2;
    red[g][q * 4 + 3] = s3;
    __syncthreads();
    if (tid < 128) {
        double S = 0.0;
#pragma unroll
        for (int g2 = 0; g2 < 16; g2++) S += red[g2][tid];
        fin[tid] = S;
    }
    __syncthreads();
    if (tid < nf) {
        double m = fin[tid] * invcnt;
        double v = fin[64 + tid] * invcnt - m * m;
        if (v < 0.0) v = 0.0;
        double inv = rsqrt(v + 1e-5);
        float sc = (float)((double)__ldg(gam + tid) * inv);
        g_s[tid] = sc;
        g_t[tid] = __ldg(bet + tid) - (float)m * sc;
    }
}

// ---------------- edge pass B: msg MLP + scatter + stats (scalar FMA) ----------------
__global__ void __launch_bounds__(TB) k_edge_b(const int* __restrict__ dst,
                                               const int* __restrict__ src,
                                               const float* __restrict__ ea,
                                               const float* __restrict__ W1,
                                               const float* __restrict__ b1,
                                               const float* __restrict__ W2,
                                               const float* __restrict__ b2) {
    __shared__ float W2s[2048];      // 32x64
    __shared__ float aT[8][2][128];
    __shared__ float red[8][128];
    int lane = threadIdx.x & 31, wib = threadIdx.x >> 5;
    int warp = (blockIdx.x * TB + threadIdx.x) >> 5;
    int nw   = (gridDim.x * TB) >> 5;

    for (int i = threadIdx.x; i < 2048; i += TB) W2s[i] = __ldg(W2 + i);

    float cw = __ldg(W1 + 128 * 32 + lane);
    float cb = __ldg(b1 + lane);
    float bs = g_s[lane], bt = g_t[lane];
    float2 bb = __ldg((const float2*)b2 + lane);
    float ss0 = 0.f, ss1 = 0.f, qq0 = 0.f, qq1 = 0.f;
    __syncthreads();

    int toggle = 0;
    for (int grp = warp; grp < N_EDGES / 4; grp += nw) {
        int e0 = grp * 4;
        int d[4], sr[4];
        float ev[4], pa[4], pb[4];
#pragma unroll
        for (int i = 0; i < 4; i++) {
            d[i]  = __ldg(dst + e0 + i);
            sr[i] = __ldg(src + e0 + i);
            ev[i] = __ldg(ea + e0 + i);
        }
#pragma unroll
        for (int i = 0; i < 4; i++) {
            pa[i] = g_Pa[d[i] * 32 + lane];
            pb[i] = g_Pb[sr[i] * 32 + lane];
        }
        float a[4];
#pragma unroll
        for (int i = 0; i < 4; i++) {
            float z = pa[i] + pb[i] + fmaf(ev[i], cw, cb);
            a[i] = fmaxf(fmaf(z, bs, bt), 0.f);
        }
        float* at = aT[wib][toggle];
        ((float4*)at)[lane] = make_float4(a[0], a[1], a[2], a[3]);
        __syncwarp();

        float o00 = bb.x, o01 = bb.y, o10 = bb.x, o11 = bb.y;
        float o20 = bb.x, o21 = bb.y, o30 = bb.x, o31 = bb.y;
#pragma unroll
        for (int k = 0; k < 32; k++) {
            float4 av = ((const float4*)at)[k];
            float2 w = ((const float2*)W2s)[k * 32 + lane];
            o00 = fmaf(av.x, w.x, o00); o01 = fmaf(av.x, w.y, o01);
            o10 = fmaf(av.y, w.x, o10); o11 = fmaf(av.y, w.y, o11);
            o20 = fmaf(av.z, w.x, o20); o21 = fmaf(av.z, w.y, o21);
            o30 = fmaf(av.w, w.x, o30); o31 = fmaf(av.w, w.y, o31);
        }
        toggle ^= 1;
        o00 = fmaxf(o00, 0.f); o01 = fmaxf(o01, 0.f);
        o10 = fmaxf(o10, 0.f); o11 = fmaxf(o11, 0.f);
        o20 = fmaxf(o20, 0.f); o21 = fmaxf(o21, 0.f);
        o30 = fmaxf(o30, 0.f); o31 = fmaxf(o31, 0.f);
        ss0 += o00 + o10 + o20 + o30;
        ss1 += o01 + o11 + o21 + o31;
        qq0 = fmaf(o00, o00, fmaf(o10, o10, fmaf(o20, o20, fmaf(o30, o30, qq0))));
        qq1 = fmaf(o01, o01, fmaf(o11, o11, fmaf(o21, o21, fmaf(o31, o31, qq1))));
        red2(g_agg + d[0] * 64 + 2 * lane, o00, o01);
        red2(g_agg + d[1] * 64 + 2 * lane, o10, o11);
        red2(g_agg + d[2] * 64 + 2 * lane, o20, o21);
        red2(g_agg + d[3] * 64 + 2 * lane, o30, o31);
    }
    red[wib][2 * lane]      = ss0;
    red[wib][2 * lane + 1]  = ss1;
    red[wib][64 + 2 * lane] = qq0;
    red[wib][65 + 2 * lane] = qq1;
    stat_epilogue(red);
}

// ---------------- node pass A: z1n = [h, aggN] @ U1 + b ; stats; self-clean agg ----------------
__global__ void __launch_bounds__(TB) k_node_a(const float* __restrict__ U1,
                                               const float* __restrict__ ub1) {
    __shared__ float xT[8][512];
    __shared__ float red[8][128];
    int lane = threadIdx.x & 31, wib = threadIdx.x >> 5;
    int warp = (blockIdx.x * TB + threadIdx.x) >> 5;
    int nw   = (gridDim.x * TB) >> 5;
    float s2a = g_s[lane], s2b = g_s[lane + 32];
    float t2a = g_t[lane], t2b = g_t[lane + 32];
    float bbz = __ldg(ub1 + lane);
    float S = 0.f, Q = 0.f;
    float* xt = xT[wib];
    for (int grp = warp; grp < N_NODES / 4; grp += nw) {
        int base = grp * 4;
        float h0[4], h1[4], a0[4], a1[4];
#pragma unroll
        for (int i = 0; i < 4; i++) {
            int n = base + i;
            h0[i] = g_h[n * 64 + lane];
            h1[i] = g_h[n * 64 + 32 + lane];
            float dg = g_deg[n];
            a0[i] = fmaf(s2a, g_agg[n * 64 + lane],      t2a * dg);
            a1[i] = fmaf(s2b, g_agg[n * 64 + 32 + lane], t2b * dg);
            g_agg[n * 64 + lane]      = 0.f;   // self-clean: next layer / next launch sees zeros
            g_agg[n * 64 + 32 + lane] = 0.f;
        }
        __syncwarp();
        ((float4*)xt)[lane]      = make_float4(h0[0], h0[1], h0[2], h0[3]);
        ((float4*)xt)[lane + 32] = make_float4(h1[0], h1[1], h1[2], h1[3]);
        ((float4*)xt)[lane + 64] = make_float4(a0[0], a0[1], a0[2], a0[3]);
        ((float4*)xt)[lane + 96] = make_float4(a1[0], a1[1], a1[2], a1[3]);
        __syncwarp();
        float z[4] = {bbz, bbz, bbz, bbz};
#pragma unroll 16
        for (int k = 0; k < 128; k++) {
            float4 xv = ((const float4*)xt)[k];
            float w = __ldg(U1 + k * 32 + lane);
            z[0] = fmaf(xv.x, w, z[0]);
            z[1] = fmaf(xv.y, w, z[1]);
            z[2] = fmaf(xv.z, w, z[2]);
            z[3] = fmaf(xv.w, w, z[3]);
        }
#pragma unroll
        for (int i = 0; i < 4; i++) {
            g_z1n[(base + i) * 32 + lane] = z[i];
            S += z[i];
            Q = fmaf(z[i], z[i], Q);
        }
    }
    red[wib][lane] = S;       red[wib][32 + lane] = 0.f;
    red[wib][64 + lane] = Q;  red[wib][96 + lane] = 0.f;
    stat_epilogue(red);
}

// ---------------- node pass B (scalar FMA) ----------------
__global__ void __launch_bounds__(TB) k_node_b(const float* __restrict__ U2,
                                               const float* __restrict__ ub2) {
    __shared__ float U2s[2048];
    __shared__ float aT[8][2][128];
    __shared__ float red[8][128];
    int lane = threadIdx.x & 31, wib = threadIdx.x >> 5;
    int warp = (blockIdx.x * TB + threadIdx.x) >> 5;
    int nw   = (gridDim.x * TB) >> 5;
    for (int i = threadIdx.x; i < 2048; i += TB) U2s[i] = __ldg(U2 + i);
    float s3 = g_s[lane], t3 = g_t[lane];
    float2 bb = __ldg((const float2*)ub2 + lane);
    float ss0 = 0.f, ss1 = 0.f, qq0 = 0.f, qq1 = 0.f;
    __syncthreads();
    int toggle = 0;
    for (int grp = warp; grp < N_NODES / 4; grp += nw) {
        int base = grp * 4;
        float a[4];
#pragma unroll
        for (int i = 0; i < 4; i++)
            a[i] = fmaxf(fmaf(g_z1n[(base + i) * 32 + lane], s3, t3), 0.f);
        float* at = aT[wib][toggle];
        ((float4*)at)[lane] = make_float4(a[0], a[1], a[2], a[3]);
        __syncwarp();
        float o00 = bb.x, o01 = bb.y, o10 = bb.x, o11 = bb.y;
        float o20 = bb.x, o21 = bb.y, o30 = bb.x, o31 = bb.y;
#pragma unroll
        for (int k = 0; k < 32; k++) {
            float4 av = ((const float4*)at)[k];
            float2 w = ((const float2*)U2s)[k * 32 + lane];
            o00 = fmaf(av.x, w.x, o00); o01 = fmaf(av.x, w.y, o01);
            o10 = fmaf(av.y, w.x, o10); o11 = fmaf(av.y, w.y, o11);
            o20 = fmaf(av.z, w.x, o20); o21 = fmaf(av.z, w.y, o21);
            o30 = fmaf(av.w, w.x, o30); o31 = fmaf(av.w, w.y, o31);
        }
        toggle ^= 1;
        o00 = fmaxf(o00, 0.f); o01 = fmaxf(o01, 0.f);
        o10 = fmaxf(o10, 0.f); o11 = fmaxf(o11, 0.f);
        o20 = fmaxf(o20, 0.f); o21 = fmaxf(o21, 0.f);
        o30 = fmaxf(o30, 0.f); o31 = fmaxf(o31, 0.f);
        ((float2*)g_a2n)[(base + 0) * 32 + lane] = make_float2(o00, o01);
        ((float2*)g_a2n)[(base + 1) * 32 + lane] = make_float2(o10, o11);
        ((float2*)g_a2n)[(base + 2) * 32 + lane] = make_float2(o20, o21);
        ((float2*)g_a2n)[(base + 3) * 32 + lane] = make_float2(o30, o31);
        ss0 += o00 + o10 + o20 + o30;
        ss1 += o01 + o11 + o21 + o31;
        qq0 = fmaf(o00, o00, fmaf(o10, o10, fmaf(o20, o20, fmaf(o30, o30, qq0))));
        qq1 = fmaf(o01, o01, fmaf(o11, o11, fmaf(o21, o21, fmaf(o31, o31, qq1))));
    }
    red[wib][2 * lane]      = ss0;
    red[wib][2 * lane + 1]  = ss1;
    red[wib][64 + 2 * lane] = qq0;
    red[wib][65 + 2 * lane] = qq1;
    stat_epilogue(red);
}

// ---------------- h += bn(a2n); project next layer ----------------
__global__ void __launch_bounds__(TB) k_update_proj(const float* __restrict__ W1next) {
    __shared__ float hT[8][256];
    int lane = threadIdx.x & 31, wib = threadIdx.x >> 5;
    int warp = (blockIdx.x * TB + threadIdx.x) >> 5;
    int nw   = (gridDim.x * TB) >> 5;
    float s4a = g_s[lane], s4b = g_s[lane + 32];
    float t4a = g_t[lane], t4b = g_t[lane + 32];
    float* ht = hT[wib];
    for (int grp = warp; grp < N_NODES / 4; grp += nw) {
        int base = grp * 4;
        float h0[4], h1[4];
#pragma unroll
        for (int i = 0; i < 4; i++) {
            int n = base + i;
            h0[i] = g_h[n * 64 + lane]      + fmaf(s4a, g_a2n[n * 64 + lane],      t4a);
            h1[i] = g_h[n * 64 + 32 + lane] + fmaf(s4b, g_a2n[n * 64 + 32 + lane], t4b);
            g_h[n * 64 + lane]      = h0[i];
            g_h[n * 64 + 32 + lane] = h1[i];
        }
        project_group(W1next, lane, ht, h0, h1, base);
    }
}

// ---------------- last layer: h += bn(a2n); pool; zero deg ----------------
__global__ void __launch_bounds__(TB) k_update_pool(const int* __restrict__ batch) {
    int lane = threadIdx.x & 31;
    int warp = (blockIdx.x * TB + threadIdx.x) >> 5;
    int nw   = (gridDim.x * TB) >> 5;
    float s4a = g_s[lane], s4b = g_s[lane + 32];
    float t4a = g_t[lane], t4b = g_t[lane + 32];
    for (int grp = warp; grp < N_NODES / 4; grp += nw) {
        int base = grp * 4;
        float h0[4], h1[4];
        int gg[4];
#pragma unroll
        for (int i = 0; i < 4; i++) {
            int n = base + i;
            h0[i] = g_h[n * 64 + lane]      + fmaf(s4a, g_a2n[n * 64 + lane],      t4a);
            h1[i] = g_h[n * 64 + 32 + lane] + fmaf(s4b, g_a2n[n * 64 + 32 + lane], t4b);
            gg[i] = __ldg(batch + n);
        }
        if (lane < 4) g_deg[base + lane] = 0.f;   // self-clean deg for next launch
        if (gg[0] == gg[3]) {  // batch sorted -> all four equal
            red1(&g_pool[gg[0] * 64 + lane],      h0[0] + h0[1] + h0[2] + h0[3]);
            red1(&g_pool[gg[0] * 64 + 32 + lane], h1[0] + h1[1] + h1[2] + h1[3]);
            if (lane == 0) red1(&g_cnt[gg[0]], 4.0f);
        } else {
#pragma unroll
            for (int i = 0; i < 4; i++) {
                red1(&g_pool[gg[i] * 64 + lane], h0[i]);
                red1(&g_pool[gg[i] * 64 + 32 + lane], h1[i]);
                if (lane == 0) red1(&g_cnt[gg[i]], 1.0f);
            }
        }
    }
}

// ---------------- final head; self-clean pool/cnt ----------------
__global__ void k_out(const float* __restrict__ ow, const float* __restrict__ ob,
                      float* __restrict__ out) {
    int lane = threadIdx.x & 31;
    int gidx = (blockIdx.x * blockDim.x + threadIdx.x) >> 5;
    if (gidx >= NGRAPH) return;
    float c = fmaxf(g_cnt[gidx], 1.0f);
    float v = g_pool[gidx * 64 + lane] * __ldg(ow + lane)
            + g_pool[gidx * 64 + 32 + lane] * __ldg(ow + lane + 32);
#pragma unroll
    for (int off = 16; off > 0; off >>= 1) v += __shfl_down_sync(0xffffffffu, v, off);
    if (lane == 0) out[gidx] = fmaxf(v / c + __ldg(ob), 0.f);
    g_pool[gidx * 64 + lane] = 0.f;
    g_pool[gidx * 64 + 32 + lane] = 0.f;
    if (lane == 0) g_cnt[gidx] = 0.f;
}

// ---------------- launch ----------------
extern "C" void kernel_launch(void* const* d_in, const int* in_sizes, int n_in,
                              void* d_out, int out_size) {
    const float* x       = (const float*)d_in[0];
    const int*   ei      = (const int*)  d_in[1];
    const float* ea      = (const float*)d_in[2];
    const int*   batch   = (const int*)  d_in[3];
    const float* lin_w   = (const float*)d_in[4];
    const float* lin_b   = (const float*)d_in[5];
    const float* msg_w1  = (const float*)d_in[6];
    const float* msg_b1  = (const float*)d_in[7];
    const float* msg_g1  = (const float*)d_in[8];
    const float* msg_be1 = (const float*)d_in[9];
    const float* msg_w2  = (const float*)d_in[10];
    const float* msg_b2  = (const float*)d_in[11];
    const float* msg_g2  = (const float*)d_in[12];
    const float* msg_be2 = (const float*)d_in[13];
    const float* upd_w1  = (const float*)d_in[14];
    const float* upd_b1  = (const float*)d_in[15];
    const float* upd_g1  = (const float*)d_in[16];
    const float* upd_be1 = (const float*)d_in[17];
    const float* upd_w2  = (const float*)d_in[18];
    const float* upd_b2  = (const float*)d_in[19];
    const float* upd_g2  = (const float*)d_in[20];
    const float* upd_be2 = (const float*)d_in[21];
    const float* out_w   = (const float*)d_in[22];
    const float* out_b   = (const float*)d_in[23];

    const int* src = ei;
    const int* dst = ei + N_EDGES;

    const double invE = 1.0 / (double)N_EDGES;
    const double invN = 1.0 / (double)N_NODES;

    k_lin_in<<<NB_STAT, TB>>>(x, lin_w, lin_b);
    k_deg<<<512, TB>>>(dst);
    k_project<<<NB_STAT, TB>>>(msg_w1);

    for (int l = 0; l < NLAYER; l++) {
        const float* W1 = msg_w1 + l * 129 * 32;
        const float* b1 = msg_b1 + l * 32;
        const float* W2 = msg_w2 + l * 32 * 64;
        const float* b2 = msg_b2 + l * 64;
        const float* U1 = upd_w1 + l * 128 * 32;
        const float* v1 = upd_b1 + l * 32;
        const float* U2 = upd_w2 + l * 32 * 64;
        const float* v2 = upd_b2 + l * 64;

        k_edge_a<<<NB_STAT, TB>>>(dst, src, ea, W1, b1);
        k_bn<<<1, 512>>>(msg_g1 + l * 32, msg_be1 + l * 32, 32, invE);
        k_edge_b<<<NB_STAT, TB>>>(dst, src, ea, W1, b1, W2, b2);
        k_bn<<<1, 512>>>(msg_g2 + l * 64, msg_be2 + l * 64, 64, invE);
        k_node_a<<<NB_STAT, TB>>>(U1, v1);
        k_bn<<<1, 512>>>(upd_g1 + l * 32, upd_be1 + l * 32, 32, invN);
        k_node_b<<<NB_STAT, TB>>>(U2, v2);
        k_bn<<<1, 512>>>(upd_g2 + l * 64, upd_be2 + l * 64, 64, invN);

        if (l == NLAYER - 1) {
            k_update_pool<<<NB_STAT, TB>>>(batch);
        } else {
            k_update_proj<<<NB_STAT, TB>>>(msg_w1 + (l + 1) * 129 * 32);
        }
    }

    k_out<<<16, 1024>>>(out_w, out_b, (float*)d_out);
}

// round 12
// speedup vs baseline: 1.4092x; 1.2725x over previous
#include <cuda_runtime.h>
#include <cstdint>

#define N_NODES 100000
#define N_EDGES 800000
#define NGRAPH  512
#define NLAYER  3
#define NB_STAT 1184
#define TB      256

// ---------------- static scratch ----------------
__device__ float g_h   [N_NODES * 64];
__device__ float g_Pa  [N_NODES * 32];
__device__ float g_Pb  [N_NODES * 32];
__device__ float g_agg [NLAYER][N_NODES * 64];
__device__ float g_z1n [N_NODES * 32];
__device__ float g_a2n [N_NODES * 64];
__device__ float g_deg [N_NODES];
__device__ float g_pool[NGRAPH * 64];
__device__ float g_cnt [NGRAPH];
__device__ float g_stat[12][128];   // per-BN-phase stat slots: [0..63]=sum, [64..127]=sumsq

// ---------------- helpers ----------------
__device__ __forceinline__ void red2(float* p, float a, float b) {
    asm volatile("red.global.add.v2.f32 [%0], {%1, %2};"
                 :: "l"(p), "f"(a), "f"(b) : "memory");
}
__device__ __forceinline__ void red1(float* p, float a) {
    asm volatile("red.global.add.f32 [%0], %1;"
                 :: "l"(p), "f"(a) : "memory");
}

// ---------------- zero accumulated scratch (incl. stat slots) ----------------
__global__ void k_zero() {
    long i  = (long)blockIdx.x * blockDim.x + threadIdx.x;
    long st = (long)gridDim.x * blockDim.x;
    float* aggf = &g_agg[0][0];
    long tot = (long)NLAYER * N_NODES * 64;
    for (long j = i; j < tot; j += st) aggf[j] = 0.f;
    for (long j = i; j < N_NODES; j += st) g_deg[j] = 0.f;
    for (long j = i; j < NGRAPH * 64; j += st) g_pool[j] = 0.f;
    for (long j = i; j < NGRAPH; j += st) g_cnt[j] = 0.f;
    if (i < 12 * 128) (&g_stat[0][0])[i] = 0.f;
}

// ---------------- producer epilogue: block-reduce + atomic into stat slot ----------------
__device__ __forceinline__ void stat_epilogue(float (*red)[128], float* slot) {
    __syncthreads();
    int f = threadIdx.x;
    if (f < 128) {
        float S = 0.f;
#pragma unroll
        for (int w = 0; w < 8; w++) S += red[w][f];
        red1(slot + f, S);
    }
}

// ---------------- consumer prologue: fold stats into (s,t) per block ----------------
__device__ __forceinline__ void bn_prologue(const float* __restrict__ slot,
                                            const float* __restrict__ gam,
                                            const float* __restrict__ bet,
                                            double invcnt, int nf,
                                            float* sS, float* sT) {
    int f = threadIdx.x;
    if (f < nf) {
        double S = (double)slot[f];
        double Q = (double)slot[64 + f];
        double m = S * invcnt;
        double v = Q * invcnt - m * m;
        if (v < 0.0) v = 0.0;
        double inv = rsqrt(v + 1e-5);
        float sc = (float)((double)__ldg(gam + f) * inv);
        sS[f] = sc;
        sT[f] = __ldg(bet + f) - (float)m * sc;
    }
}

// ---------------- h = x @ Win + b ----------------
__global__ void __launch_bounds__(TB) k_lin_in(const float* __restrict__ x,
                                               const float* __restrict__ W,
                                               const float* __restrict__ b) {
    int lane = threadIdx.x & 31;
    int warp = (blockIdx.x * TB + threadIdx.x) >> 5;
    int nw   = (gridDim.x * TB) >> 5;
    float b0 = __ldg(b + lane), b1 = __ldg(b + 32 + lane);
    for (int n = warp; n < N_NODES; n += nw) {
        float h0 = b0, h1 = b1;
#pragma unroll
        for (int k = 0; k < 16; k++) {
            float xv = __ldg(x + n * 16 + k);
            h0 = fmaf(xv, __ldg(W + k * 64 + lane), h0);
            h1 = fmaf(xv, __ldg(W + k * 64 + 32 + lane), h1);
        }
        g_h[n * 64 + lane] = h0;
        g_h[n * 64 + 32 + lane] = h1;
    }
}

// ---------------- in-degree ----------------
__global__ void k_deg(const int* __restrict__ dst) {
    int i = blockIdx.x * blockDim.x + threadIdx.x;
    int st = gridDim.x * blockDim.x;
    for (int e = i; e < N_EDGES; e += st) red1(&g_deg[__ldg(dst + e)], 1.0f);
}

// ---------------- project h -> Pa,Pb (LDS.128 broadcast GEMM, scalar FMA) ----------------
__device__ __forceinline__ void project_group(const float* __restrict__ W1, int lane,
                                              float* ht, const float h0[4], const float h1[4],
                                              int base) {
    __syncwarp();
    ((float4*)ht)[lane]      = make_float4(h0[0], h0[1], h0[2], h0[3]);
    ((float4*)ht)[lane + 32] = make_float4(h1[0], h1[1], h1[2], h1[3]);
    __syncwarp();
    float pa[4] = {0, 0, 0, 0}, pb[4] = {0, 0, 0, 0};
#pragma unroll 16
    for (int k = 0; k < 64; k++) {
        float4 hv = ((const float4*)ht)[k];
        float wa = __ldg(W1 + k * 32 + lane);
        float wb = __ldg(W1 + (64 + k) * 32 + lane);
        pa[0] = fmaf(hv.x, wa, pa[0]); pb[0] = fmaf(hv.x, wb, pb[0]);
        pa[1] = fmaf(hv.y, wa, pa[1]); pb[1] = fmaf(hv.y, wb, pb[1]);
        pa[2] = fmaf(hv.z, wa, pa[2]); pb[2] = fmaf(hv.z, wb, pb[2]);
        pa[3] = fmaf(hv.w, wa, pa[3]); pb[3] = fmaf(hv.w, wb, pb[3]);
    }
#pragma unroll
    for (int i = 0; i < 4; i++) {
        g_Pa[(base + i) * 32 + lane] = pa[i];
        g_Pb[(base + i) * 32 + lane] = pb[i];
    }
}

__global__ void __launch_bounds__(TB) k_project(const float* __restrict__ W1) {
    __shared__ float hT[8][256];
    int lane = threadIdx.x & 31, wib = threadIdx.x >> 5;
    int warp = (blockIdx.x * TB + threadIdx.x) >> 5;
    int nw   = (gridDim.x * TB) >> 5;
    float* ht = hT[wib];
    for (int grp = warp; grp < N_NODES / 4; grp += nw) {
        int base = grp * 4;
        float h0[4], h1[4];
#pragma unroll
        for (int i = 0; i < 4; i++) {
            h0[i] = g_h[(base + i) * 64 + lane];
            h1[i] = g_h[(base + i) * 64 + 32 + lane];
        }
        project_group(W1, lane, ht, h0, h1, base);
    }
}

// ---------------- edge pass A: stats of z1 (8 edges/warp-iter) -> slot m1 ----------------
__global__ void __launch_bounds__(TB) k_edge_a(const int* __restrict__ dst,
                                               const int* __restrict__ src,
                                               const float* __restrict__ ea,
                                               const float* __restrict__ W1,
                                               const float* __restrict__ b1,
                                               float* slot_m1) {
    __shared__ float red[8][128];
    int lane = threadIdx.x & 31, wib = threadIdx.x >> 5;
    int warp = (blockIdx.x * TB + threadIdx.x) >> 5;
    int nw   = (gridDim.x * TB) >> 5;
    float cw = __ldg(W1 + 128 * 32 + lane);
    float cb = __ldg(b1 + lane);
    float S = 0.f, Q = 0.f;
    for (int grp = warp; grp < N_EDGES / 8; grp += nw) {
        int e0 = grp * 8;
        int d[8], s[8];
        float ev[8], pa[8], pb[8];
#pragma unroll
        for (int i = 0; i < 8; i++) {
            d[i] = __ldg(dst + e0 + i);
            s[i] = __ldg(src + e0 + i);
            ev[i] = __ldg(ea + e0 + i);
        }
#pragma unroll
        for (int i = 0; i < 8; i++) pa[i] = g_Pa[d[i] * 32 + lane];
#pragma unroll
        for (int i = 0; i < 8; i++) pb[i] = g_Pb[s[i] * 32 + lane];
#pragma unroll
        for (int i = 0; i < 8; i++) {
            float z = pa[i] + pb[i] + fmaf(ev[i], cw, cb);
            S += z;
            Q = fmaf(z, z, Q);
        }
    }
    red[wib][lane] = S;       red[wib][32 + lane] = 0.f;
    red[wib][64 + lane] = Q;  red[wib][96 + lane] = 0.f;
    stat_epilogue(red, slot_m1);
}

// ---------------- edge pass B: consume m1; msg MLP + scatter; produce m2 ----------------
__global__ void __launch_bounds__(TB) k_edge_b(const int* __restrict__ dst,
                                               const int* __restrict__ src,
                                               const float* __restrict__ ea,
                                               const float* __restrict__ W1,
                                               const float* __restrict__ b1,
                                               const float* __restrict__ W2,
                                               const float* __restrict__ b2,
                                               const float* __restrict__ gam1,
                                               const float* __restrict__ bet1,
                                               const float* slot_m1,
                                               float* slot_m2,
                                               double invE, int layer) {
    __shared__ float W2s[2048];
    __shared__ float aT[8][2][128];
    __shared__ float red[8][128];
    __shared__ float sS[64], sT[64];
    int lane = threadIdx.x & 31, wib = threadIdx.x >> 5;
    int warp = (blockIdx.x * TB + threadIdx.x) >> 5;
    int nw   = (gridDim.x * TB) >> 5;
    float* agg = &g_agg[layer][0];

    bn_prologue(slot_m1, gam1, bet1, invE, 32, sS, sT);
    for (int i = threadIdx.x; i < 2048; i += TB) W2s[i] = __ldg(W2 + i);

    float cw = __ldg(W1 + 128 * 32 + lane);
    float cb = __ldg(b1 + lane);
    float2 bb = __ldg((const float2*)b2 + lane);
    float ss0 = 0.f, ss1 = 0.f, qq0 = 0.f, qq1 = 0.f;
    __syncthreads();
    float bs = sS[lane], bt = sT[lane];

    int toggle = 0;
    for (int grp = warp; grp < N_EDGES / 4; grp += nw) {
        int e0 = grp * 4;
        int d[4], sr[4];
        float ev[4], pa[4], pb[4];
#pragma unroll
        for (int i = 0; i < 4; i++) {
            d[i]  = __ldg(dst + e0 + i);
            sr[i] = __ldg(src + e0 + i);
            ev[i] = __ldg(ea + e0 + i);
        }
#pragma unroll
        for (int i = 0; i < 4; i++) {
            pa[i] = g_Pa[d[i] * 32 + lane];
            pb[i] = g_Pb[sr[i] * 32 + lane];
        }
        float a[4];
#pragma unroll
        for (int i = 0; i < 4; i++) {
            float z = pa[i] + pb[i] + fmaf(ev[i], cw, cb);
            a[i] = fmaxf(fmaf(z, bs, bt), 0.f);
        }
        float* at = aT[wib][toggle];
        ((float4*)at)[lane] = make_float4(a[0], a[1], a[2], a[3]);
        __syncwarp();

        float o00 = bb.x, o01 = bb.y, o10 = bb.x, o11 = bb.y;
        float o20 = bb.x, o21 = bb.y, o30 = bb.x, o31 = bb.y;
#pragma unroll
        for (int k = 0; k < 32; k++) {
            float4 av = ((const float4*)at)[k];
            float2 w = ((const float2*)W2s)[k * 32 + lane];
            o00 = fmaf(av.x, w.x, o00); o01 = fmaf(av.x, w.y, o01);
            o10 = fmaf(av.y, w.x, o10); o11 = fmaf(av.y, w.y, o11);
            o20 = fmaf(av.z, w.x, o20); o21 = fmaf(av.z, w.y, o21);
            o30 = fmaf(av.w, w.x, o30); o31 = fmaf(av.w, w.y, o31);
        }
        toggle ^= 1;
        o00 = fmaxf(o00, 0.f); o01 = fmaxf(o01, 0.f);
        o10 = fmaxf(o10, 0.f); o11 = fmaxf(o11, 0.f);
        o20 = fmaxf(o20, 0.f); o21 = fmaxf(o21, 0.f);
        o30 = fmaxf(o30, 0.f); o31 = fmaxf(o31, 0.f);
        ss0 += o00 + o10 + o20 + o30;
        ss1 += o01 + o11 + o21 + o31;
        qq0 = fmaf(o00, o00, fmaf(o10, o10, fmaf(o20, o20, fmaf(o30, o30, qq0))));
        qq1 = fmaf(o01, o01, fmaf(o11, o11, fmaf(o21, o21, fmaf(o31, o31, qq1))));
        red2(agg + d[0] * 64 + 2 * lane, o00, o01);
        red2(agg + d[1] * 64 + 2 * lane, o10, o11);
        red2(agg + d[2] * 64 + 2 * lane, o20, o21);
        red2(agg + d[3] * 64 + 2 * lane, o30, o31);
    }
    red[wib][2 * lane]      = ss0;
    red[wib][2 * lane + 1]  = ss1;
    red[wib][64 + 2 * lane] = qq0;
    red[wib][65 + 2 * lane] = qq1;
    stat_epilogue(red, slot_m2);
}

// ---------------- node pass A: consume m2; z1n GEMM; produce u1 ----------------
__global__ void __launch_bounds__(TB) k_node_a(const float* __restrict__ U1,
                                               const float* __restrict__ ub1,
                                               const float* __restrict__ gam2,
                                               const float* __restrict__ bet2,
                                               const float* slot_m2,
                                               float* slot_u1,
                                               double invE, int layer) {
    __shared__ float xT[8][512];
    __shared__ float red[8][128];
    __shared__ float sS[64], sT[64];
    int lane = threadIdx.x & 31, wib = threadIdx.x >> 5;
    int warp = (blockIdx.x * TB + threadIdx.x) >> 5;
    int nw   = (gridDim.x * TB) >> 5;
    const float* agg = &g_agg[layer][0];

    bn_prologue(slot_m2, gam2, bet2, invE, 64, sS, sT);
    float bbz = __ldg(ub1 + lane);
    __syncthreads();
    float s2a = sS[lane], s2b = sS[lane + 32];
    float t2a = sT[lane], t2b = sT[lane + 32];

    float S = 0.f, Q = 0.f;
    float* xt = xT[wib];
    for (int grp = warp; grp < N_NODES / 4; grp += nw) {
        int base = grp * 4;
        float h0[4], h1[4], a0[4], a1[4];
#pragma unroll
        for (int i = 0; i < 4; i++) {
            int n = base + i;
            h0[i] = g_h[n * 64 + lane];
            h1[i] = g_h[n * 64 + 32 + lane];
            float dg = g_deg[n];
            a0[i] = fmaf(s2a, agg[n * 64 + lane],      t2a * dg);
            a1[i] = fmaf(s2b, agg[n * 64 + 32 + lane], t2b * dg);
        }
        __syncwarp();
        ((float4*)xt)[lane]      = make_float4(h0[0], h0[1], h0[2], h0[3]);
        ((float4*)xt)[lane + 32] = make_float4(h1[0], h1[1], h1[2], h1[3]);
        ((float4*)xt)[lane + 64] = make_float4(a0[0], a0[1], a0[2], a0[3]);
        ((float4*)xt)[lane + 96] = make_float4(a1[0], a1[1], a1[2], a1[3]);
        __syncwarp();
        float z[4] = {bbz, bbz, bbz, bbz};
#pragma unroll 16
        for (int k = 0; k < 128; k++) {
            float4 xv = ((const float4*)xt)[k];
            float w = __ldg(U1 + k * 32 + lane);
            z[0] = fmaf(xv.x, w, z[0]);
            z[1] = fmaf(xv.y, w, z[1]);
            z[2] = fmaf(xv.z, w, z[2]);
            z[3] = fmaf(xv.w, w, z[3]);
        }
#pragma unroll
        for (int i = 0; i < 4; i++) {
            g_z1n[(base + i) * 32 + lane] = z[i];
            S += z[i];
            Q = fmaf(z[i], z[i], Q);
        }
    }
    red[wib][lane] = S;       red[wib][32 + lane] = 0.f;
    red[wib][64 + lane] = Q;  red[wib][96 + lane] = 0.f;
    stat_epilogue(red, slot_u1);
}

// ---------------- node pass B: consume u1; produce u2 ----------------
__global__ void __launch_bounds__(TB) k_node_b(const float* __restrict__ U2,
                                               const float* __restrict__ ub2,
                                               const float* __restrict__ gam1,
                                               const float* __restrict__ bet1,
                                               const float* slot_u1,
                                               float* slot_u2,
                                               double invN) {
    __shared__ float U2s[2048];
    __shared__ float aT[8][2][128];
    __shared__ float red[8][128];
    __shared__ float sS[64], sT[64];
    int lane = threadIdx.x & 31, wib = threadIdx.x >> 5;
    int warp = (blockIdx.x * TB + threadIdx.x) >> 5;
    int nw   = (gridDim.x * TB) >> 5;

    bn_prologue(slot_u1, gam1, bet1, invN, 32, sS, sT);
    for (int i = threadIdx.x; i < 2048; i += TB) U2s[i] = __ldg(U2 + i);
    float2 bb = __ldg((const float2*)ub2 + lane);
    float ss0 = 0.f, ss1 = 0.f, qq0 = 0.f, qq1 = 0.f;
    __syncthreads();
    float s3 = sS[lane], t3 = sT[lane];

    int toggle = 0;
    for (int grp = warp; grp < N_NODES / 4; grp += nw) {
        int base = grp * 4;
        float a[4];
#pragma unroll
        for (int i = 0; i < 4; i++)
            a[i] = fmaxf(fmaf(g_z1n[(base + i) * 32 + lane], s3, t3), 0.f);
        float* at = aT[wib][toggle];
        ((float4*)at)[lane] = make_float4(a[0], a[1], a[2], a[3]);
        __syncwarp();
        float o00 = bb.x, o01 = bb.y, o10 = bb.x, o11 = bb.y;
        float o20 = bb.x, o21 = bb.y, o30 = bb.x, o31 = bb.y;
#pragma unroll
        for (int k = 0; k < 32; k++) {
            float4 av = ((const float4*)at)[k];
            float2 w = ((const float2*)U2s)[k * 32 + lane];
            o00 = fmaf(av.x, w.x, o00); o01 = fmaf(av.x, w.y, o01);
            o10 = fmaf(av.y, w.x, o10); o11 = fmaf(av.y, w.y, o11);
            o20 = fmaf(av.z, w.x, o20); o21 = fmaf(av.z, w.y, o21);
            o30 = fmaf(av.w, w.x, o30); o31 = fmaf(av.w, w.y, o31);
        }
        toggle ^= 1;
        o00 = fmaxf(o00, 0.f); o01 = fmaxf(o01, 0.f);
        o10 = fmaxf(o10, 0.f); o11 = fmaxf(o11, 0.f);
        o20 = fmaxf(o20, 0.f); o21 = fmaxf(o21, 0.f);
        o30 = fmaxf(o30, 0.f); o31 = fmaxf(o31, 0.f);
        ((float2*)g_a2n)[(base + 0) * 32 + lane] = make_float2(o00, o01);
        ((float2*)g_a2n)[(base + 1) * 32 + lane] = make_float2(o10, o11);
        ((float2*)g_a2n)[(base + 2) * 32 + lane] = make_float2(o20, o21);
        ((float2*)g_a2n)[(base + 3) * 32 + lane] = make_float2(o30, o31);
        ss0 += o00 + o10 + o20 + o30;
        ss1 += o01 + o11 + o21 + o31;
        qq0 = fmaf(o00, o00, fmaf(o10, o10, fmaf(o20, o20, fmaf(o30, o30, qq0))));
        qq1 = fmaf(o01, o01, fmaf(o11, o11, fmaf(o21, o21, fmaf(o31, o31, qq1))));
    }
    red[wib][2 * lane]      = ss0;
    red[wib][2 * lane + 1]  = ss1;
    red[wib][64 + 2 * lane] = qq0;
    red[wib][65 + 2 * lane] = qq1;
    stat_epilogue(red, slot_u2);
}

// ---------------- consume u2: h += bn(a2n); project next layer ----------------
__global__ void __launch_bounds__(TB) k_update_proj(const float* __restrict__ W1next,
                                                    const float* __restrict__ gam2,
                                                    const float* __restrict__ bet2,
                                                    const float* slot_u2,
                                                    double invN) {
    __shared__ float hT[8][256];
    __shared__ float sS[64], sT[64];
    int lane = threadIdx.x & 31, wib = threadIdx.x >> 5;
    int warp = (blockIdx.x * TB + threadIdx.x) >> 5;
    int nw   = (gridDim.x * TB) >> 5;
    bn_prologue(slot_u2, gam2, bet2, invN, 64, sS, sT);
    __syncthreads();
    float s4a = sS[lane], s4b = sS[lane + 32];
    float t4a = sT[lane], t4b = sT[lane + 32];
    float* ht = hT[wib];
    for (int grp = warp; grp < N_NODES / 4; grp += nw) {
        int base = grp * 4;
        float h0[4], h1[4];
#pragma unroll
        for (int i = 0; i < 4; i++) {
            int n = base + i;
            h0[i] = g_h[n * 64 + lane]      + fmaf(s4a, g_a2n[n * 64 + lane],      t4a);
            h1[i] = g_h[n * 64 + 32 + lane] + fmaf(s4b, g_a2n[n * 64 + 32 + lane], t4b);
            g_h[n * 64 + lane]      = h0[i];
            g_h[n * 64 + 32 + lane] = h1[i];
        }
        project_group(W1next, lane, ht, h0, h1, base);
    }
}

// ---------------- consume u2 (last layer): h += bn(a2n); mean-pool scatter ----------------
__global__ void __launch_bounds__(TB) k_update_pool(const int* __restrict__ batch,
                                                    const float* __restrict__ gam2,
                                                    const float* __restrict__ bet2,
                                                    const float* slot_u2,
                                                    double invN) {
    __shared__ float sS[64], sT[64];
    int lane = threadIdx.x & 31;
    int warp = (blockIdx.x * TB + threadIdx.x) >> 5;
    int nw   = (gridDim.x * TB) >> 5;
    bn_prologue(slot_u2, gam2, bet2, invN, 64, sS, sT);
    __syncthreads();
    float s4a = sS[lane], s4b = sS[lane + 32];
    float t4a = sT[lane], t4b = sT[lane + 32];
    for (int grp = warp; grp < N_NODES / 4; grp += nw) {
        int base = grp * 4;
        float h0[4], h1[4];
        int gg[4];
#pragma unroll
        for (int i = 0; i < 4; i++) {
            int n = base + i;
            h0[i] = g_h[n * 64 + lane]      + fmaf(s4a, g_a2n[n * 64 + lane],      t4a);
            h1[i] = g_h[n * 64 + 32 + lane] + fmaf(s4b, g_a2n[n * 64 + 32 + lane], t4b);
            gg[i] = __ldg(batch + n);
        }
        if (gg[0] == gg[3]) {  // batch sorted -> all four equal
            red1(&g_pool[gg[0] * 64 + lane],      h0[0] + h0[1] + h0[2] + h0[3]);
            red1(&g_pool[gg[0] * 64 + 32 + lane], h1[0] + h1[1] + h1[2] + h1[3]);
            if (lane == 0) red1(&g_cnt[gg[0]], 4.0f);
        } else {
#pragma unroll
            for (int i = 0; i < 4; i++) {
                red1(&g_pool[gg[i] * 64 + lane], h0[i]);
                red1(&g_pool[gg[i] * 64 + 32 + lane], h1[i]);
                if (lane == 0) red1(&g_cnt[gg[i]], 1.0f);
            }
        }
    }
}

// ---------------- final head ----------------
__global__ void k_out(const float* __restrict__ ow, const float* __restrict__ ob,
                      float* __restrict__ out) {
    int lane = threadIdx.x & 31;
    int gidx = (blockIdx.x * blockDim.x + threadIdx.x) >> 5;
    if (gidx >= NGRAPH) return;
    float c = fmaxf(g_cnt[gidx], 1.0f);
    float v = g_pool[gidx * 64 + lane] * __ldg(ow + lane)
            + g_pool[gidx * 64 + 32 + lane] * __ldg(ow + lane + 32);
#pragma unroll
    for (int off = 16; off > 0; off >>= 1) v += __shfl_down_sync(0xffffffffu, v, off);
    if (lane == 0) out[gidx] = fmaxf(v / c + __ldg(ob), 0.f);
}

// ---------------- launch ----------------
extern "C" void kernel_launch(void* const* d_in, const int* in_sizes, int n_in,
                              void* d_out, int out_size) {
    const float* x       = (const float*)d_in[0];
    const int*   ei      = (const int*)  d_in[1];
    const float* ea      = (const float*)d_in[2];
    const int*   batch   = (const int*)  d_in[3];
    const float* lin_w   = (const float*)d_in[4];
    const float* lin_b   = (const float*)d_in[5];
    const float* msg_w1  = (const float*)d_in[6];
    const float* msg_b1  = (const float*)d_in[7];
    const float* msg_g1  = (const float*)d_in[8];
    const float* msg_be1 = (const float*)d_in[9];
    const float* msg_w2  = (const float*)d_in[10];
    const float* msg_b2  = (const float*)d_in[11];
    const float* msg_g2  = (const float*)d_in[12];
    const float* msg_be2 = (const float*)d_in[13];
    const float* upd_w1  = (const float*)d_in[14];
    const float* upd_b1  = (const float*)d_in[15];
    const float* upd_g1  = (const float*)d_in[16];
    const float* upd_be1 = (const float*)d_in[17];
    const float* upd_w2  = (const float*)d_in[18];
    const float* upd_b2  = (const float*)d_in[19];
    const float* upd_g2  = (const float*)d_in[20];
    const float* upd_be2 = (const float*)d_in[21];
    const float* out_w   = (const float*)d_in[22];
    const float* out_b   = (const float*)d_in[23];

    const int* src = ei;
    const int* dst = ei + N_EDGES;

    const double invE = 1.0 / (double)N_EDGES;
    const double invN = 1.0 / (double)N_NODES;

    float* statbase;
    cudaGetSymbolAddress((void**)&statbase, g_stat);

    k_zero<<<512, TB>>>();
    k_lin_in<<<NB_STAT, TB>>>(x, lin_w, lin_b);
    k_deg<<<512, TB>>>(dst);
    k_project<<<NB_STAT, TB>>>(msg_w1);

    for (int l = 0; l < NLAYER; l++) {
        const float* W1 = msg_w1 + l * 129 * 32;
        const float* b1 = msg_b1 + l * 32;
        const float* W2 = msg_w2 + l * 32 * 64;
        const float* b2 = msg_b2 + l * 64;
        const float* U1 = upd_w1 + l * 128 * 32;
        const float* v1 = upd_b1 + l * 32;
        const float* U2 = upd_w2 + l * 32 * 64;
        const float* v2 = upd_b2 + l * 64;
        float* m1 = statbase + (l * 4 + 0) * 128;
        float* m2 = statbase + (l * 4 + 1) * 128;
        float* u1 = statbase + (l * 4 + 2) * 128;
        float* u2 = statbase + (l * 4 + 3) * 128;

        k_edge_a<<<NB_STAT, TB>>>(dst, src, ea, W1, b1, m1);
        k_edge_b<<<NB_STAT, TB>>>(dst, src, ea, W1, b1, W2, b2,
                                  msg_g1 + l * 32, msg_be1 + l * 32, m1, m2, invE, l);
        k_node_a<<<NB_STAT, TB>>>(U1, v1, msg_g2 + l * 64, msg_be2 + l * 64,
                                  m2, u1, invE, l);
        k_node_b<<<NB_STAT, TB>>>(U2, v2, upd_g1 + l * 32, upd_be1 + l * 32,
                                  u1, u2, invN);
        if (l == NLAYER - 1) {
            k_update_pool<<<NB_STAT, TB>>>(batch, upd_g2 + l * 64, upd_be2 + l * 64,
                                           u2, invN);
        } else {
            k_update_proj<<<NB_STAT, TB>>>(msg_w1 + (l + 1) * 129 * 32,
                                           upd_g2 + l * 64, upd_be2 + l * 64,
                                           u2, invN);
        }
    }

    k_out<<<16, 1024>>>(out_w, out_b, (float*)d_out);
}

// round 14
// speedup vs baseline: 1.4217x; 1.0089x over previous
#include <cuda_runtime.h>
#include <cstdint>

// Round 14 = round 13 resubmitted (driver-side Trio flake, no data), minus one
// leftover no-op red1(...,0.f) line in k_edge_a.

#define N_NODES 100000
#define N_EDGES 800000
#define NGRAPH  512
#define NLAYER  3
#define NB_STAT 1184
#define TB      256

// ---------------- static scratch ----------------
__device__ float g_h   [N_NODES * 64];
__device__ float g_Pa  [N_NODES * 32];
__device__ float g_Pb  [N_NODES * 32];
__device__ float g_agg [NLAYER][N_NODES * 64];
__device__ float g_z1n [N_NODES * 32];
__device__ float g_a2n [N_NODES * 64];
__device__ float g_deg [N_NODES];
__device__ float g_pool[NGRAPH * 64];
__device__ float g_cnt [NGRAPH];
__device__ float g_stat[12][128];   // per-BN-phase stat slots: [0..63]=sum, [64..127]=sumsq

// ---------------- helpers ----------------
__device__ __forceinline__ void red2(float* p, float a, float b) {
    asm volatile("red.global.add.v2.f32 [%0], {%1, %2};"
                 :: "l"(p), "f"(a), "f"(b) : "memory");
}
__device__ __forceinline__ void red1(float* p, float a) {
    asm volatile("red.global.add.f32 [%0], %1;"
                 :: "l"(p), "f"(a) : "memory");
}

// ---------------- zero accumulated scratch (incl. stat slots) ----------------
__global__ void k_zero() {
    long i  = (long)blockIdx.x * blockDim.x + threadIdx.x;
    long st = (long)gridDim.x * blockDim.x;
    float* aggf = &g_agg[0][0];
    long tot = (long)NLAYER * N_NODES * 64;
    for (long j = i; j < tot; j += st) aggf[j] = 0.f;
    for (long j = i; j < N_NODES; j += st) g_deg[j] = 0.f;
    for (long j = i; j < NGRAPH * 64; j += st) g_pool[j] = 0.f;
    for (long j = i; j < NGRAPH; j += st) g_cnt[j] = 0.f;
    if (i < 12 * 128) (&g_stat[0][0])[i] = 0.f;
}

// ---------------- producer epilogue: block-reduce + atomic into stat slot ----------------
__device__ __forceinline__ void stat_epilogue(float (*red)[128], float* slot) {
    __syncthreads();
    int f = threadIdx.x;
    if (f < 128) {
        float S = 0.f;
#pragma unroll
        for (int w = 0; w < 8; w++) S += red[w][f];
        red1(slot + f, S);
    }
}

// ---------------- consumer prologue: fold stats into (s,t) per block ----------------
__device__ __forceinline__ void bn_prologue(const float* __restrict__ slot,
                                            const float* __restrict__ gam,
                                            const float* __restrict__ bet,
                                            double invcnt, int nf,
                                            float* sS, float* sT) {
    int f = threadIdx.x;
    if (f < nf) {
        double S = (double)slot[f];
        double Q = (double)slot[64 + f];
        double m = S * invcnt;
        double v = Q * invcnt - m * m;
        if (v < 0.0) v = 0.0;
        double inv = rsqrt(v + 1e-5);
        float sc = (float)((double)__ldg(gam + f) * inv);
        sS[f] = sc;
        sT[f] = __ldg(bet + f) - (float)m * sc;
    }
}

// ---------------- project h -> Pa,Pb (LDS.128 broadcast GEMM, scalar FMA) ----------------
__device__ __forceinline__ void project_group(const float* __restrict__ W1, int lane,
                                              float* ht, const float h0[4], const float h1[4],
                                              int base) {
    __syncwarp();
    ((float4*)ht)[lane]      = make_float4(h0[0], h0[1], h0[2], h0[3]);
    ((float4*)ht)[lane + 32] = make_float4(h1[0], h1[1], h1[2], h1[3]);
    __syncwarp();
    float pa[4] = {0, 0, 0, 0}, pb[4] = {0, 0, 0, 0};
#pragma unroll 16
    for (int k = 0; k < 64; k++) {
        float4 hv = ((const float4*)ht)[k];
        float wa = __ldg(W1 + k * 32 + lane);
        float wb = __ldg(W1 + (64 + k) * 32 + lane);
        pa[0] = fmaf(hv.x, wa, pa[0]); pb[0] = fmaf(hv.x, wb, pb[0]);
        pa[1] = fmaf(hv.y, wa, pa[1]); pb[1] = fmaf(hv.y, wb, pb[1]);
        pa[2] = fmaf(hv.z, wa, pa[2]); pb[2] = fmaf(hv.z, wb, pb[2]);
        pa[3] = fmaf(hv.w, wa, pa[3]); pb[3] = fmaf(hv.w, wb, pb[3]);
    }
#pragma unroll
    for (int i = 0; i < 4; i++) {
        g_Pa[(base + i) * 32 + lane] = pa[i];
        g_Pb[(base + i) * 32 + lane] = pb[i];
    }
}

// ---------------- fused: h = x @ Win + b, then Pa/Pb projection (layer 0) ----------------
__global__ void __launch_bounds__(TB) k_lin_proj(const float* __restrict__ x,
                                                 const float* __restrict__ Wi,
                                                 const float* __restrict__ bi,
                                                 const float* __restrict__ W1) {
    __shared__ float hT[8][256];
    int lane = threadIdx.x & 31, wib = threadIdx.x >> 5;
    int warp = (blockIdx.x * TB + threadIdx.x) >> 5;
    int nw   = (gridDim.x * TB) >> 5;
    float b0 = __ldg(bi + lane), b1 = __ldg(bi + 32 + lane);
    float* ht = hT[wib];
    for (int grp = warp; grp < N_NODES / 4; grp += nw) {
        int base = grp * 4;
        float h0[4], h1[4];
#pragma unroll
        for (int i = 0; i < 4; i++) {
            int n = base + i;
            float a0 = b0, a1 = b1;
#pragma unroll
            for (int k = 0; k < 16; k++) {
                float xv = __ldg(x + n * 16 + k);
                a0 = fmaf(xv, __ldg(Wi + k * 64 + lane), a0);
                a1 = fmaf(xv, __ldg(Wi + k * 64 + 32 + lane), a1);
            }
            h0[i] = a0; h1[i] = a1;
            g_h[n * 64 + lane] = a0;
            g_h[n * 64 + 32 + lane] = a1;
        }
        project_group(W1, lane, ht, h0, h1, base);
    }
}

// ---------------- edge pass A: stats of z1 (8 edges/warp-iter) -> slot m1; deg on layer0 ----------------
__global__ void __launch_bounds__(TB) k_edge_a(const int* __restrict__ dst,
                                               const int* __restrict__ src,
                                               const float* __restrict__ ea,
                                               const float* __restrict__ W1,
                                               const float* __restrict__ b1,
                                               float* slot_m1, int do_deg) {
    __shared__ float red[8][128];
    int lane = threadIdx.x & 31, wib = threadIdx.x >> 5;
    int warp = (blockIdx.x * TB + threadIdx.x) >> 5;
    int nw   = (gridDim.x * TB) >> 5;
    float cw = __ldg(W1 + 128 * 32 + lane);
    float cb = __ldg(b1 + lane);
    float S = 0.f, Q = 0.f;
    for (int grp = warp; grp < N_EDGES / 8; grp += nw) {
        int e0 = grp * 8;
        int d[8], s[8];
        float ev[8], pa[8], pb[8];
#pragma unroll
        for (int i = 0; i < 8; i++) {
            d[i] = __ldg(dst + e0 + i);
            s[i] = __ldg(src + e0 + i);
            ev[i] = __ldg(ea + e0 + i);
        }
        if (do_deg && lane < 8) {
            int dd = __ldg(dst + e0 + lane);
            red1(&g_deg[dd], 1.0f);
        }
#pragma unroll
        for (int i = 0; i < 8; i++) pa[i] = g_Pa[d[i] * 32 + lane];
#pragma unroll
        for (int i = 0; i < 8; i++) pb[i] = g_Pb[s[i] * 32 + lane];
#pragma unroll
        for (int i = 0; i < 8; i++) {
            float z = pa[i] + pb[i] + fmaf(ev[i], cw, cb);
            S += z;
            Q = fmaf(z, z, Q);
        }
    }
    red[wib][lane] = S;       red[wib][32 + lane] = 0.f;
    red[wib][64 + lane] = Q;  red[wib][96 + lane] = 0.f;
    stat_epilogue(red, slot_m1);
}

// ---------------- edge pass B: consume m1; msg MLP + scatter; produce m2 ----------------
__global__ void __launch_bounds__(TB) k_edge_b(const int* __restrict__ dst,
                                               const int* __restrict__ src,
                                               const float* __restrict__ ea,
                                               const float* __restrict__ W1,
                                               const float* __restrict__ b1,
                                               const float* __restrict__ W2,
                                               const float* __restrict__ b2,
                                               const float* __restrict__ gam1,
                                               const float* __restrict__ bet1,
                                               const float* slot_m1,
                                               float* slot_m2,
                                               double invE, int layer) {
    __shared__ float W2s[2048];
    __shared__ float aT[8][2][128];
    __shared__ float red[8][128];
    __shared__ float sS[64], sT[64];
    int lane = threadIdx.x & 31, wib = threadIdx.x >> 5;
    int warp = (blockIdx.x * TB + threadIdx.x) >> 5;
    int nw   = (gridDim.x * TB) >> 5;
    float* agg = &g_agg[layer][0];

    bn_prologue(slot_m1, gam1, bet1, invE, 32, sS, sT);
    for (int i = threadIdx.x; i < 2048; i += TB) W2s[i] = __ldg(W2 + i);

    float cw = __ldg(W1 + 128 * 32 + lane);
    float cb = __ldg(b1 + lane);
    float2 bb = __ldg((const float2*)b2 + lane);
    float ss0 = 0.f, ss1 = 0.f, qq0 = 0.f, qq1 = 0.f;
    __syncthreads();
    float bs = sS[lane], bt = sT[lane];

    int toggle = 0;
    for (int grp = warp; grp < N_EDGES / 4; grp += nw) {
        int e0 = grp * 4;
        int d[4], sr[4];
        float ev[4], pa[4], pb[4];
#pragma unroll
        for (int i = 0; i < 4; i++) {
            d[i]  = __ldg(dst + e0 + i);
            sr[i] = __ldg(src + e0 + i);
            ev[i] = __ldg(ea + e0 + i);
        }
#pragma unroll
        for (int i = 0; i < 4; i++) {
            pa[i] = g_Pa[d[i] * 32 + lane];
            pb[i] = g_Pb[sr[i] * 32 + lane];
        }
        float a[4];
#pragma unroll
        for (int i = 0; i < 4; i++) {
            float z = pa[i] + pb[i] + fmaf(ev[i], cw, cb);
            a[i] = fmaxf(fmaf(z, bs, bt), 0.f);
        }
        float* at = aT[wib][toggle];
        ((float4*)at)[lane] = make_float4(a[0], a[1], a[2], a[3]);
        __syncwarp();

        float o00 = bb.x, o01 = bb.y, o10 = bb.x, o11 = bb.y;
        float o20 = bb.x, o21 = bb.y, o30 = bb.x, o31 = bb.y;
#pragma unroll
        for (int k = 0; k < 32; k++) {
            float4 av = ((const float4*)at)[k];
            float2 w = ((const float2*)W2s)[k * 32 + lane];
            o00 = fmaf(av.x, w.x, o00); o01 = fmaf(av.x, w.y, o01);
            o10 = fmaf(av.y, w.x, o10); o11 = fmaf(av.y, w.y, o11);
            o20 = fmaf(av.z, w.x, o20); o21 = fmaf(av.z, w.y, o21);
            o30 = fmaf(av.w, w.x, o30); o31 = fmaf(av.w, w.y, o31);
        }
        toggle ^= 1;
        o00 = fmaxf(o00, 0.f); o01 = fmaxf(o01, 0.f);
        o10 = fmaxf(o10, 0.f); o11 = fmaxf(o11, 0.f);
        o20 = fmaxf(o20, 0.f); o21 = fmaxf(o21, 0.f);
        o30 = fmaxf(o30, 0.f); o31 = fmaxf(o31, 0.f);
        ss0 += o00 + o10 + o20 + o30;
        ss1 += o01 + o11 + o21 + o31;
        qq0 = fmaf(o00, o00, fmaf(o10, o10, fmaf(o20, o20, fmaf(o30, o30, qq0))));
        qq1 = fmaf(o01, o01, fmaf(o11, o11, fmaf(o21, o21, fmaf(o31, o31, qq1))));
        red2(agg + d[0] * 64 + 2 * lane, o00, o01);
        red2(agg + d[1] * 64 + 2 * lane, o10, o11);
        red2(agg + d[2] * 64 + 2 * lane, o20, o21);
        red2(agg + d[3] * 64 + 2 * lane, o30, o31);
    }
    red[wib][2 * lane]      = ss0;
    red[wib][2 * lane + 1]  = ss1;
    red[wib][64 + 2 * lane] = qq0;
    red[wib][65 + 2 * lane] = qq1;
    stat_epilogue(red, slot_m2);
}

// ---------------- node pass A: consume m2; z1n GEMM; produce u1 ----------------
__global__ void __launch_bounds__(TB) k_node_a(const float* __restrict__ U1,
                                               const float* __restrict__ ub1,
                                               const float* __restrict__ gam2,
                                               const float* __restrict__ bet2,
                                               const float* slot_m2,
                                               float* slot_u1,
                                               double invE, int layer) {
    __shared__ float xT[8][512];
    __shared__ float red[8][128];
    __shared__ float sS[64], sT[64];
    int lane = threadIdx.x & 31, wib = threadIdx.x >> 5;
    int warp = (blockIdx.x * TB + threadIdx.x) >> 5;
    int nw   = (gridDim.x * TB) >> 5;
    const float* agg = &g_agg[layer][0];

    bn_prologue(slot_m2, gam2, bet2, invE, 64, sS, sT);
    float bbz = __ldg(ub1 + lane);
    __syncthreads();
    float s2a = sS[lane], s2b = sS[lane + 32];
    float t2a = sT[lane], t2b = sT[lane + 32];

    float S = 0.f, Q = 0.f;
    float* xt = xT[wib];
    for (int grp = warp; grp < N_NODES / 4; grp += nw) {
        int base = grp * 4;
        float h0[4], h1[4], a0[4], a1[4];
#pragma unroll
        for (int i = 0; i < 4; i++) {
            int n = base + i;
            h0[i] = g_h[n * 64 + lane];
            h1[i] = g_h[n * 64 + 32 + lane];
            float dg = g_deg[n];
            a0[i] = fmaf(s2a, agg[n * 64 + lane],      t2a * dg);
            a1[i] = fmaf(s2b, agg[n * 64 + 32 + lane], t2b * dg);
        }
        __syncwarp();
        ((float4*)xt)[lane]      = make_float4(h0[0], h0[1], h0[2], h0[3]);
        ((float4*)xt)[lane + 32] = make_float4(h1[0], h1[1], h1[2], h1[3]);
        ((float4*)xt)[lane + 64] = make_float4(a0[0], a0[1], a0[2], a0[3]);
        ((float4*)xt)[lane + 96] = make_float4(a1[0], a1[1], a1[2], a1[3]);
        __syncwarp();
        float z[4] = {bbz, bbz, bbz, bbz};
#pragma unroll 16
        for (int k = 0; k < 128; k++) {
            float4 xv = ((const float4*)xt)[k];
            float w = __ldg(U1 + k * 32 + lane);
            z[0] = fmaf(xv.x, w, z[0]);
            z[1] = fmaf(xv.y, w, z[1]);
            z[2] = fmaf(xv.z, w, z[2]);
            z[3] = fmaf(xv.w, w, z[3]);
        }
#pragma unroll
        for (int i = 0; i < 4; i++) {
            g_z1n[(base + i) * 32 + lane] = z[i];
            S += z[i];
            Q = fmaf(z[i], z[i], Q);
        }
    }
    red[wib][lane] = S;       red[wib][32 + lane] = 0.f;
    red[wib][64 + lane] = Q;  red[wib][96 + lane] = 0.f;
    stat_epilogue(red, slot_u1);
}

// ---------------- node pass B: consume u1; produce u2 ----------------
__global__ void __launch_bounds__(TB) k_node_b(const float* __restrict__ U2,
                                               const float* __restrict__ ub2,
                                               const float* __restrict__ gam1,
                                               const float* __restrict__ bet1,
                                               const float* slot_u1,
                                               float* slot_u2,
                                               double invN) {
    __shared__ float U2s[2048];
    __shared__ float aT[8][2][128];
    __shared__ float red[8][128];
    __shared__ float sS[64], sT[64];
    int lane = threadIdx.x & 31, wib = threadIdx.x >> 5;
    int warp = (blockIdx.x * TB + threadIdx.x) >> 5;
    int nw   = (gridDim.x * TB) >> 5;

    bn_prologue(slot_u1, gam1, bet1, invN, 32, sS, sT);
    for (int i = threadIdx.x; i < 2048; i += TB) U2s[i] = __ldg(U2 + i);
    float2 bb = __ldg((const float2*)ub2 + lane);
    float ss0 = 0.f, ss1 = 0.f, qq0 = 0.f, qq1 = 0.f;
    __syncthreads();
    float s3 = sS[lane], t3 = sT[lane];

    int toggle = 0;
    for (int grp = warp; grp < N_NODES / 4; grp += nw) {
        int base = grp * 4;
        float a[4];
#pragma unroll
        for (int i = 0; i < 4; i++)
            a[i] = fmaxf(fmaf(g_z1n[(base + i) * 32 + lane], s3, t3), 0.f);
        float* at = aT[wib][toggle];
        ((float4*)at)[lane] = make_float4(a[0], a[1], a[2], a[3]);
        __syncwarp();
        float o00 = bb.x, o01 = bb.y, o10 = bb.x, o11 = bb.y;
        float o20 = bb.x, o21 = bb.y, o30 = bb.x, o31 = bb.y;
#pragma unroll
        for (int k = 0; k < 32; k++) {
            float4 av = ((const float4*)at)[k];
            float2 w = ((const float2*)U2s)[k * 32 + lane];
            o00 = fmaf(av.x, w.x, o00); o01 = fmaf(av.x, w.y, o01);
            o10 = fmaf(av.y, w.x, o10); o11 = fmaf(av.y, w.y, o11);
            o20 = fmaf(av.z, w.x, o20); o21 = fmaf(av.z, w.y, o21);
            o30 = fmaf(av.w, w.x, o30); o31 = fmaf(av.w, w.y, o31);
        }
        toggle ^= 1;
        o00 = fmaxf(o00, 0.f); o01 = fmaxf(o01, 0.f);
        o10 = fmaxf(o10, 0.f); o11 = fmaxf(o11, 0.f);
        o20 = fmaxf(o20, 0.f); o21 = fmaxf(o21, 0.f);
        o30 = fmaxf(o30, 0.f); o31 = fmaxf(o31, 0.f);
        ((float2*)g_a2n)[(base + 0) * 32 + lane] = make_float2(o00, o01);
        ((float2*)g_a2n)[(base + 1) * 32 + lane] = make_float2(o10, o11);
        ((float2*)g_a2n)[(base + 2) * 32 + lane] = make_float2(o20, o21);
        ((float2*)g_a2n)[(base + 3) * 32 + lane] = make_float2(o30, o31);
        ss0 += o00 + o10 + o20 + o30;
        ss1 += o01 + o11 + o21 + o31;
        qq0 = fmaf(o00, o00, fmaf(o10, o10, fmaf(o20, o20, fmaf(o30, o30, qq0))));
        qq1 = fmaf(o01, o01, fmaf(o11, o11, fmaf(o21, o21, fmaf(o31, o31, qq1))));
    }
    red[wib][2 * lane]      = ss0;
    red[wib][2 * lane + 1]  = ss1;
    red[wib][64 + 2 * lane] = qq0;
    red[wib][65 + 2 * lane] = qq1;
    stat_epilogue(red, slot_u2);
}

// ---------------- consume u2: h += bn(a2n); project next layer ----------------
__global__ void __launch_bounds__(TB) k_update_proj(const float* __restrict__ W1next,
                                                    const float* __restrict__ gam2,
                                                    const float* __restrict__ bet2,
                                                    const float* slot_u2,
                                                    double invN) {
    __shared__ float hT[8][256];
    __shared__ float sS[64], sT[64];
    int lane = threadIdx.x & 31, wib = threadIdx.x >> 5;
    int warp = (blockIdx.x * TB + threadIdx.x) >> 5;
    int nw   = (gridDim.x * TB) >> 5;
    bn_prologue(slot_u2, gam2, bet2, invN, 64, sS, sT);
    __syncthreads();
    float s4a = sS[lane], s4b = sS[lane + 32];
    float t4a = sT[lane], t4b = sT[lane + 32];
    float* ht = hT[wib];
    for (int grp = warp; grp < N_NODES / 4; grp += nw) {
        int base = grp * 4;
        float h0[4], h1[4];
#pragma unroll
        for (int i = 0; i < 4; i++) {
            int n = base + i;
            h0[i] = g_h[n * 64 + lane]      + fmaf(s4a, g_a2n[n * 64 + lane],      t4a);
            h1[i] = g_h[n * 64 + 32 + lane] + fmaf(s4b, g_a2n[n * 64 + 32 + lane], t4b);
            g_h[n * 64 + lane]      = h0[i];
            g_h[n * 64 + 32 + lane] = h1[i];
        }
        project_group(W1next, lane, ht, h0, h1, base);
    }
}

// ---------------- consume u2 (last layer): h += bn(a2n); mean-pool scatter ----------------
__global__ void __launch_bounds__(TB) k_update_pool(const int* __restrict__ batch,
                                                    const float* __restrict__ gam2,
                                                    const float* __restrict__ bet2,
                                                    const float* slot_u2,
                                                    double invN) {
    __shared__ float sS[64], sT[64];
    int lane = threadIdx.x & 31;
    int warp = (blockIdx.x * TB + threadIdx.x) >> 5;
    int nw   = (gridDim.x * TB) >> 5;
    bn_prologue(slot_u2, gam2, bet2, invN, 64, sS, sT);
    __syncthreads();
    float s4a = sS[lane], s4b = sS[lane + 32];
    float t4a = sT[lane], t4b = sT[lane + 32];
    for (int grp = warp; grp < N_NODES / 4; grp += nw) {
        int base = grp * 4;
        float h0[4], h1[4];
        int gg[4];
#pragma unroll
        for (int i = 0; i < 4; i++) {
            int n = base + i;
            h0[i] = g_h[n * 64 + lane]      + fmaf(s4a, g_a2n[n * 64 + lane],      t4a);
            h1[i] = g_h[n * 64 + 32 + lane] + fmaf(s4b, g_a2n[n * 64 + 32 + lane], t4b);
            gg[i] = __ldg(batch + n);
        }
        if (gg[0] == gg[3]) {  // batch sorted -> all four equal
            red1(&g_pool[gg[0] * 64 + lane],      h0[0] + h0[1] + h0[2] + h0[3]);
            red1(&g_pool[gg[0] * 64 + 32 + lane], h1[0] + h1[1] + h1[2] + h1[3]);
            if (lane == 0) red1(&g_cnt[gg[0]], 4.0f);
        } else {
#pragma unroll
            for (int i = 0; i < 4; i++) {
                red1(&g_pool[gg[i] * 64 + lane], h0[i]);
                red1(&g_pool[gg[i] * 64 + 32 + lane], h1[i]);
                if (lane == 0) red1(&g_cnt[gg[i]], 1.0f);
            }
        }
    }
}

// ---------------- final head ----------------
__global__ void k_out(const float* __restrict__ ow, const float* __restrict__ ob,
                      float* __restrict__ out) {
    int lane = threadIdx.x & 31;
    int gidx = (blockIdx.x * blockDim.x + threadIdx.x) >> 5;
    if (gidx >= NGRAPH) return;
    float c = fmaxf(g_cnt[gidx], 1.0f);
    float v = g_pool[gidx * 64 + lane] * __ldg(ow + lane)
            + g_pool[gidx * 64 + 32 + lane] * __ldg(ow + lane + 32);
#pragma unroll
    for (int off = 16; off > 0; off >>= 1) v += __shfl_down_sync(0xffffffffu, v, off);
    if (lane == 0) out[gidx] = fmaxf(v / c + __ldg(ob), 0.f);
}

// ---------------- launch ----------------
extern "C" void kernel_launch(void* const* d_in, const int* in_sizes, int n_in,
                              void* d_out, int out_size) {
    const float* x       = (const float*)d_in[0];
    const int*   ei      = (const int*)  d_in[1];
    const float* ea      = (const float*)d_in[2];
    const int*   batch   = (const int*)  d_in[3];
    const float* lin_w   = (const float*)d_in[4];
    const float* lin_b   = (const float*)d_in[5];
    const float* msg_w1  = (const float*)d_in[6];
    const float* msg_b1  = (const float*)d_in[7];
    const float* msg_g1  = (const float*)d_in[8];
    const float* msg_be1 = (const float*)d_in[9];
    const float* msg_w2  = (const float*)d_in[10];
    const float* msg_b2  = (const float*)d_in[11];
    const float* msg_g2  = (const float*)d_in[12];
    const float* msg_be2 = (const float*)d_in[13];
    const float* upd_w1  = (const float*)d_in[14];
    const float* upd_b1  = (const float*)d_in[15];
    const float* upd_g1  = (const float*)d_in[16];
    const float* upd_be1 = (const float*)d_in[17];
    const float* upd_w2  = (const float*)d_in[18];
    const float* upd_b2  = (const float*)d_in[19];
    const float* upd_g2  = (const float*)d_in[20];
    const float* upd_be2 = (const float*)d_in[21];
    const float* out_w   = (const float*)d_in[22];
    const float* out_b   = (const float*)d_in[23];

    const int* src = ei;
    const int* dst = ei + N_EDGES;

    const double invE = 1.0 / (double)N_EDGES;
    const double invN = 1.0 / (double)N_NODES;

    float* statbase;
    cudaGetSymbolAddress((void**)&statbase, g_stat);

    k_zero<<<512, TB>>>();
    k_lin_proj<<<NB_STAT, TB>>>(x, lin_w, lin_b, msg_w1);

    for (int l = 0; l < NLAYER; l++) {
        const float* W1 = msg_w1 + l * 129 * 32;
        const float* b1 = msg_b1 + l * 32;
        const float* W2 = msg_w2 + l * 32 * 64;
        const float* b2 = msg_b2 + l * 64;
        const float* U1 = upd_w1 + l * 128 * 32;
        const float* v1 = upd_b1 + l * 32;
        const float* U2 = upd_w2 + l * 32 * 64;
        const float* v2 = upd_b2 + l * 64;
        float* m1 = statbase + (l * 4 + 0) * 128;
        float* m2 = statbase + (l * 4 + 1) * 128;
        float* u1 = statbase + (l * 4 + 2) * 128;
        float* u2 = statbase + (l * 4 + 3) * 128;

        k_edge_a<<<NB_STAT, TB>>>(dst, src, ea, W1, b1, m1, l == 0 ? 1 : 0);
        k_edge_b<<<NB_STAT, TB>>>(dst, src, ea, W1, b1, W2, b2,
                                  msg_g1 + l * 32, msg_be1 + l * 32, m1, m2, invE, l);
        k_node_a<<<NB_STAT, TB>>>(U1, v1, msg_g2 + l * 64, msg_be2 + l * 64,
                                  m2, u1, invE, l);
        k_node_b<<<NB_STAT, TB>>>(U2, v2, upd_g1 + l * 32, upd_be1 + l * 32,
                                  u1, u2, invN);
        if (l == NLAYER - 1) {
            k_update_pool<<<NB_STAT, TB>>>(batch, upd_g2 + l * 64, upd_be2 + l * 64,
                                           u2, invN);
        } else {
            k_update_proj<<<NB_STAT, TB>>>(msg_w1 + (l + 1) * 129 * 32,
                                           upd_g2 + l * 64, upd_be2 + l * 64,
                                           u2, invN);
        }
    }

    k_out<<<16, 1024>>>(out_w, out_b, (float*)d_out);
}